// round 12
// baseline (speedup 1.0000x reference)
#include <cuda_runtime.h>
#include <cuda_bf16.h>
#include <math_constants.h>
#include <cstdint>

// Problem constants
#define B_  2
#define T_  2048
#define C_  1024
#define H_  16
#define D_  64
#define M_  (B_*T_)          // 4096 rows
#define BHTD (B_*H_*T_*D_)
#define KP_ (3*C_)           // 3072 split-K

// Scratch (device globals, referenced directly from kernels)
__device__ float g_q[BHTD];
__device__ float g_k[BHTD];
__device__ __nv_bfloat16 g_qs[(size_t)BHTD*2];       // q split [bh][t][hi64|lo64]
__device__ __nv_bfloat16 g_ks[(size_t)BHTD*2];       // k split
__device__ __nv_bfloat16 g_vs[(size_t)BHTD*2];       // v split
__device__ __nv_bfloat16 g_xs[(size_t)M_ * KP_];     // x split      [4096,3072]
__device__ __nv_bfloat16 g_ws[(size_t)3*C_ * KP_];   // W_attn split  [3072,3072]
__device__ __nv_bfloat16 g_ys[(size_t)M_ * KP_];     // y split       [4096,3072]
__device__ __nv_bfloat16 g_wps[(size_t)C_ * KP_];    // W_proj split  [1024,3072]

// ---------------------------------------------------------------------------
// fp32 -> bf16 hi/lo splits packed along K'=3K=3072.
// A-side: [hi, hi, lo];  B-side: [hi, lo, hi]  =>  hi*hi + hi*lo + lo*hi
// ---------------------------------------------------------------------------
__global__ void split_x_kernel(const float* __restrict__ src)
{
    int idx = blockIdx.x * blockDim.x + threadIdx.x;
    if (idx >= M_*C_/4) return;
    float4 v = ((const float4*)src)[idx];
    int r = idx >> 8;
    int k = (idx & 255) * 4;
    float vv[4] = {v.x, v.y, v.z, v.w};
    size_t base = (size_t)r * KP_ + k;
#pragma unroll
    for (int i = 0; i < 4; i++) {
        __nv_bfloat16 hi = __float2bfloat16(vv[i]);
        __nv_bfloat16 lo = __float2bfloat16(vv[i] - __bfloat162float(hi));
        g_xs[base + i]        = hi;
        g_xs[base + C_ + i]   = hi;
        g_xs[base + 2*C_ + i] = lo;
    }
}

__global__ void split_w_kernel(const float* __restrict__ src)
{
    int idx = blockIdx.x * blockDim.x + threadIdx.x;
    if (idx >= 3*C_*C_/4) return;
    float4 v = ((const float4*)src)[idx];
    int r = idx >> 8;
    int k = (idx & 255) * 4;
    float vv[4] = {v.x, v.y, v.z, v.w};
    size_t base = (size_t)r * KP_ + k;
#pragma unroll
    for (int i = 0; i < 4; i++) {
        __nv_bfloat16 hi = __float2bfloat16(vv[i]);
        __nv_bfloat16 lo = __float2bfloat16(vv[i] - __bfloat162float(hi));
        g_ws[base + i]        = hi;
        g_ws[base + C_ + i]   = lo;
        g_ws[base + 2*C_ + i] = hi;
    }
}

__global__ void split_wp_kernel(const float* __restrict__ src)
{
    int idx = blockIdx.x * blockDim.x + threadIdx.x;
    if (idx >= C_*C_/4) return;
    float4 v = ((const float4*)src)[idx];
    int r = idx >> 8;
    int k = (idx & 255) * 4;
    float vv[4] = {v.x, v.y, v.z, v.w};
    size_t base = (size_t)r * KP_ + k;
#pragma unroll
    for (int i = 0; i < 4; i++) {
        __nv_bfloat16 hi = __float2bfloat16(vv[i]);
        __nv_bfloat16 lo = __float2bfloat16(vv[i] - __bfloat162float(hi));
        g_wps[base + i]        = hi;
        g_wps[base + C_ + i]   = lo;
        g_wps[base + 2*C_ + i] = hi;
    }
}

// ---------------------------------------------------------------------------
// Tensor-core GEMM over pre-split operands (proven R9).
// 256x128 tile, 512 threads (16 warps: 8 M x 2 N, warp 32x64),
// 4-stage cp.async pipeline (single sync per tile), ldmatrix.x4 fragments.
// MODE 1: g_xs * g_ws^T + b_attn -> q,k fp32 [B,H,T,D]; v split bf16 g_vs
// MODE 0: g_ys * g_wps^T + b_proj -> out row-major [M,1024]
// ---------------------------------------------------------------------------
#define SSTRIDE 40
#define GSTAGES 4
#define GEMM_SMEM ((GSTAGES*(256+128)*SSTRIDE)*2)

#define MMA16816(C4, A0,A1,A2,A3, B0,B1)                                      \
    asm volatile(                                                             \
        "mma.sync.aligned.m16n8k16.row.col.f32.bf16.bf16.f32 "                \
        "{%0,%1,%2,%3}, {%4,%5,%6,%7}, {%8,%9}, {%0,%1,%2,%3};\n"             \
        : "+f"((C4)[0]), "+f"((C4)[1]), "+f"((C4)[2]), "+f"((C4)[3])          \
        : "r"(A0), "r"(A1), "r"(A2), "r"(A3), "r"(B0), "r"(B1))

#define LDSM_X4(R0,R1,R2,R3, ptr)                                             \
    do {                                                                      \
        unsigned int _a = (unsigned int)__cvta_generic_to_shared(ptr);        \
        asm volatile(                                                         \
            "ldmatrix.sync.aligned.m8n8.x4.shared.b16 {%0,%1,%2,%3}, [%4];\n" \
            : "=r"(R0), "=r"(R1), "=r"(R2), "=r"(R3) : "r"(_a));              \
    } while (0)

#define CP_ASYNC16(smem_u32, gptr)                                            \
    asm volatile("cp.async.cg.shared.global [%0], [%1], 16;\n"                \
                 :: "r"(smem_u32), "l"(gptr))

template<int MODE>
__global__ void __launch_bounds__(512) mma_gemm(
    const float* __restrict__ bias, float* __restrict__ out)
{
    const __nv_bfloat16* A  = (MODE == 1) ? g_xs : g_ys;
    const __nv_bfloat16* Bw = (MODE == 1) ? g_ws : g_wps;
    const int N = (MODE == 1) ? 3*C_ : C_;

    extern __shared__ __align__(16) __nv_bfloat16 gsm[];
    __nv_bfloat16* As = gsm;                          // [GSTAGES][256*SSTRIDE]
    __nv_bfloat16* Bs = gsm + GSTAGES*256*SSTRIDE;    // [GSTAGES][128*SSTRIDE]

    const int tid  = threadIdx.x;
    const int wid  = tid >> 5;
    const int lane = tid & 31;
    const int m0 = blockIdx.y * 256;
    const int n0 = blockIdx.x * 128;
    const int wm = (wid >> 1) * 32;
    const int wn = (wid & 1) * 64;
    const int lrow = lane & 15;
    const int lcol = (lane >> 4) << 3;

    const __nv_bfloat16* Ag = A  + (size_t)m0 * KP_;
    const __nv_bfloat16* Bg = Bw + (size_t)n0 * KP_;

    const int brow = tid >> 2, bseg = tid & 3;

    float c[2][8][4];
#pragma unroll
    for (int i = 0; i < 2; i++)
#pragma unroll
        for (int j = 0; j < 8; j++)
#pragma unroll
            for (int r = 0; r < 4; r++) c[i][j][r] = 0.f;

    const int nt = KP_ / 32;   // 96

#define ISSUE_STAGE(stage, k0)                                                \
    do {                                                                      \
        __nv_bfloat16* asb = As + (stage)*256*SSTRIDE;                        \
        __nv_bfloat16* bsb = Bs + (stage)*128*SSTRIDE;                        \
        _Pragma("unroll")                                                     \
        for (int i = 0; i < 2; i++) {                                         \
            int idx = tid + 512*i, row = idx >> 2, seg = idx & 3;             \
            unsigned int sa = (unsigned int)__cvta_generic_to_shared(         \
                &asb[row*SSTRIDE + seg*8]);                                   \
            CP_ASYNC16(sa, Ag + (size_t)row*KP_ + (k0) + seg*8);              \
        }                                                                     \
        {                                                                     \
            unsigned int sb = (unsigned int)__cvta_generic_to_shared(         \
                &bsb[brow*SSTRIDE + bseg*8]);                                 \
            CP_ASYNC16(sb, Bg + (size_t)brow*KP_ + (k0) + bseg*8);            \
        }                                                                     \
        asm volatile("cp.async.commit_group;\n");                             \
    } while (0)

    ISSUE_STAGE(0, 0);
    ISSUE_STAGE(1, 32);
    ISSUE_STAGE(2, 64);

    for (int kt = 0; kt < nt; kt++) {
        const int stage = kt % GSTAGES;
        asm volatile("cp.async.wait_group %0;\n" :: "n"(2));
        __syncthreads();   // stage kt visible; prior reads of (kt+3)%4 done

        if (kt + 3 < nt) {
            ISSUE_STAGE((kt + 3) % GSTAGES, (kt + 3) * 32);
        }

        const __nv_bfloat16* asb = As + stage*256*SSTRIDE;
        const __nv_bfloat16* bsb = Bs + stage*128*SSTRIDE;

#pragma unroll
        for (int ks = 0; ks < 2; ks++) {
            const int k16 = ks * 16;
            unsigned int af[2][4];
#pragma unroll
            for (int mi = 0; mi < 2; mi++) {
                LDSM_X4(af[mi][0], af[mi][1], af[mi][2], af[mi][3],
                        &asb[(wm + mi*16 + lrow)*SSTRIDE + k16 + lcol]);
            }
            unsigned int bm[4][4];
#pragma unroll
            for (int p = 0; p < 4; p++) {
                LDSM_X4(bm[p][0], bm[p][1], bm[p][2], bm[p][3],
                        &bsb[(wn + p*16 + lrow)*SSTRIDE + k16 + lcol]);
            }
#pragma unroll
            for (int mi = 0; mi < 2; mi++)
#pragma unroll
                for (int p = 0; p < 4; p++) {
                    MMA16816(c[mi][2*p],   af[mi][0], af[mi][1], af[mi][2], af[mi][3],
                             bm[p][0], bm[p][2]);
                    MMA16816(c[mi][2*p+1], af[mi][0], af[mi][1], af[mi][2], af[mi][3],
                             bm[p][1], bm[p][3]);
                }
        }
    }
#undef ISSUE_STAGE

#pragma unroll
    for (int mi = 0; mi < 2; mi++) {
#pragma unroll
        for (int nj = 0; nj < 8; nj++) {
            int row = m0 + wm + mi*16 + (lane >> 2);
            int col = n0 + wn + nj*8 + (lane & 3)*2;
            float b0 = bias[col], b1 = bias[col+1];
            float2 v0 = { c[mi][nj][0] + b0, c[mi][nj][1] + b1 };
            float2 v1 = { c[mi][nj][2] + b0, c[mi][nj][3] + b1 };
            if (MODE == 0) {
                *(float2*)&out[(size_t)row*N + col]     = v0;
                *(float2*)&out[(size_t)(row+8)*N + col] = v1;
            } else {
                int which = col >> 10;
                int h = (col & 1023) >> 6;
                int d = col & 63;
                int b = row >> 11, t = row & 2047;
                if (which == 2) {
                    size_t vb0 = ((size_t)(b*H_ + h)*T_ + t    )*128 + d;
                    size_t vb1 = ((size_t)(b*H_ + h)*T_ + t + 8)*128 + d;
                    __nv_bfloat162 h0, l0, h1, l1;
                    h0.x = __float2bfloat16(v0.x);
                    h0.y = __float2bfloat16(v0.y);
                    l0.x = __float2bfloat16(v0.x - __bfloat162float(h0.x));
                    l0.y = __float2bfloat16(v0.y - __bfloat162float(h0.y));
                    h1.x = __float2bfloat16(v1.x);
                    h1.y = __float2bfloat16(v1.y);
                    l1.x = __float2bfloat16(v1.x - __bfloat162float(h1.x));
                    l1.y = __float2bfloat16(v1.y - __bfloat162float(h1.y));
                    *(__nv_bfloat162*)&g_vs[vb0]      = h0;
                    *(__nv_bfloat162*)&g_vs[vb0 + 64] = l0;
                    *(__nv_bfloat162*)&g_vs[vb1]      = h1;
                    *(__nv_bfloat162*)&g_vs[vb1 + 64] = l1;
                } else {
                    float* dst = (which == 0) ? g_q : g_k;
                    size_t base0 = ((size_t)(b*H_ + h)*T_ + t    )*D_ + d;
                    size_t base1 = ((size_t)(b*H_ + h)*T_ + t + 8)*D_ + d;
                    *(float2*)&dst[base0] = v0;
                    *(float2*)&dst[base1] = v1;
                }
            }
        }
    }
}

// ---------------------------------------------------------------------------
// RoPE on q,k (fp32 in) -> split bf16 [hi64|lo64] rows out (g_qs, g_ks).
// ---------------------------------------------------------------------------
__global__ void rope_kernel()
{
    int idx = blockIdx.x * blockDim.x + threadIdx.x;
    int d  = idx & 31;
    int t  = (idx >> 5) & (T_ - 1);
    int bh = idx >> 16;
    size_t base = ((size_t)bh * T_ + t) * D_;
    size_t ob   = ((size_t)bh * T_ + t) * 128;

    const float L2_10000_OVER_32 = 13.287712379549449f / 32.0f;
    float f = exp2f(-(float)d * L2_10000_OVER_32);
    float ang = (float)t * f;
    float s, cc;
    sincosf(ang, &s, &cc);

    float q1 = g_q[base + d], q2 = g_q[base + d + 32];
    float o1 = q1*cc - q2*s;
    float o2 = q2*cc + q1*s;
    __nv_bfloat16 h1 = __float2bfloat16(o1);
    __nv_bfloat16 h2 = __float2bfloat16(o2);
    g_qs[ob + d]           = h1;
    g_qs[ob + d + 32]      = h2;
    g_qs[ob + 64 + d]      = __float2bfloat16(o1 - __bfloat162float(h1));
    g_qs[ob + 64 + d + 32] = __float2bfloat16(o2 - __bfloat162float(h2));

    float k1 = g_k[base + d], k2 = g_k[base + d + 32];
    o1 = k1*cc - k2*s;
    o2 = k2*cc + k1*s;
    h1 = __float2bfloat16(o1);
    h2 = __float2bfloat16(o2);
    g_ks[ob + d]           = h1;
    g_ks[ob + d + 32]      = h2;
    g_ks[ob + 64 + d]      = __float2bfloat16(o1 - __bfloat162float(h1));
    g_ks[ob + 64 + d + 32] = __float2bfloat16(o2 - __bfloat162float(h2));
}

// ---------------------------------------------------------------------------
// Tensor-core causal flash attention over pre-split bf16 q/k/v (proven R9).
// NEW: __launch_bounds__(256, 2) -> 2 CTAs/SM so one CTA's softmax (MUFU/ALU)
// overlaps the other CTA's MMA stream.
// ---------------------------------------------------------------------------
#define QST 136
#define KST 136
#define VST 72
#define SC_ 0.125f
#define ATTN_SMEM ((128*QST + 64*KST + 128*VST) * 2)

__global__ void __launch_bounds__(256, 2) attn_mma()
{
    extern __shared__ __align__(16) __nv_bfloat16 smA[];
    __nv_bfloat16* Qs = smA;              // [128][QST]: [q_hi(64) | q_lo(64)]
    __nv_bfloat16* Ks = Qs + 128*QST;     // [64][KST]:  [k_hi | k_lo]
    __nv_bfloat16* Vs = Ks + 64*KST;      // [128][VST]: rows 0-63 v_hi, 64-127 v_lo

    const int qt  = (int)gridDim.x - 1 - (int)blockIdx.x;
    const int bh  = blockIdx.y;
    const int tid = threadIdx.x;
    const int wid = tid >> 5;
    const int lane = tid & 31;
    const int lg = lane >> 2;
    const int lq = lane & 3;
    const int lrow = lane & 15;
    const int lcol = (lane >> 4) << 3;

    const __nv_bfloat16* qsrc = g_qs + ((size_t)bh*T_ + qt*128)*128;
#pragma unroll
    for (int i = 0; i < 8; i++) {
        int idx = tid + i*256;
        int r = idx >> 4, u = (idx & 15) * 8;
        *(uint4*)&Qs[r*QST + u] = *(const uint4*)&qsrc[r*128 + u];
    }

    float m2[2] = {-CUDART_INF_F, -CUDART_INF_F};
    float l2[2] = {0.f, 0.f};
    float oc[8][4];
#pragma unroll
    for (int j = 0; j < 8; j++)
#pragma unroll
        for (int r = 0; r < 4; r++) oc[j][r] = 0.f;

    const int jmax = 2*qt + 1;
    for (int jt = 0; jt <= jmax; jt++) {
        __syncthreads();
        const __nv_bfloat16* ksrc = g_ks + ((size_t)bh*T_ + jt*64)*128;
        const __nv_bfloat16* vsrc = g_vs + ((size_t)bh*T_ + jt*64)*128;
#pragma unroll
        for (int i = 0; i < 4; i++) {
            int idx = tid + i*256;
            int r = idx >> 4, u = idx & 15;
            *(uint4*)&Ks[r*KST + u*8] = *(const uint4*)&ksrc[r*128 + u*8];
            if (u < 8)
                *(uint4*)&Vs[r*VST + u*8] = *(const uint4*)&vsrc[r*128 + u*8];
            else
                *(uint4*)&Vs[(r+64)*VST + (u-8)*8] = *(const uint4*)&vsrc[r*128 + u*8];
        }
        __syncthreads();

        float sc[8][4];
#pragma unroll
        for (int j = 0; j < 8; j++)
#pragma unroll
            for (int r = 0; r < 4; r++) sc[j][r] = 0.f;

#pragma unroll
        for (int ks = 0; ks < 12; ks++) {
            int kk16 = (ks & 3) * 16;
            int Aoff = (ks >= 8) ? 64 : 0;
            int Boff = (ks >= 4 && ks < 8) ? 64 : 0;
            unsigned int af[4];
            LDSM_X4(af[0], af[1], af[2], af[3],
                    &Qs[(wid*16 + lrow)*QST + Aoff + kk16 + lcol]);
#pragma unroll
            for (int p = 0; p < 4; p++) {
                unsigned int bm0, bm1, bm2, bm3;
                LDSM_X4(bm0, bm1, bm2, bm3,
                        &Ks[(p*16 + lrow)*KST + Boff + kk16 + lcol]);
                MMA16816(sc[2*p],   af[0], af[1], af[2], af[3], bm0, bm2);
                MMA16816(sc[2*p+1], af[0], af[1], af[2], af[3], bm1, bm3);
            }
        }

        const bool needmask = (jt >= 2*qt);
        float rowm[2] = {-CUDART_INF_F, -CUDART_INF_F};
#pragma unroll
        for (int nj = 0; nj < 8; nj++) {
            if (needmask) {
                int kg  = jt*64 + nj*8 + lq*2;
                int qr0 = qt*128 + wid*16 + lg;
#pragma unroll
                for (int e = 0; e < 4; e++) {
                    if (kg + (e & 1) > qr0 + (e >> 1)*8) sc[nj][e] = -CUDART_INF_F;
                }
            }
            rowm[0] = fmaxf(rowm[0], fmaxf(sc[nj][0], sc[nj][1]));
            rowm[1] = fmaxf(rowm[1], fmaxf(sc[nj][2], sc[nj][3]));
        }
#pragma unroll
        for (int off = 1; off <= 2; off <<= 1) {
            rowm[0] = fmaxf(rowm[0], __shfl_xor_sync(0xffffffffu, rowm[0], off));
            rowm[1] = fmaxf(rowm[1], __shfl_xor_sync(0xffffffffu, rowm[1], off));
        }
        float corr[2];
#pragma unroll
        for (int h = 0; h < 2; h++) {
            float mn = fmaxf(m2[h], rowm[h]);
            corr[h] = __expf((m2[h] - mn) * SC_);
            m2[h] = mn;
        }
        float rs[2] = {0.f, 0.f};
        unsigned int ph[8][2], pl[8][2];
#pragma unroll
        for (int nj = 0; nj < 8; nj++) {
            float p0 = __expf((sc[nj][0] - m2[0]) * SC_);
            float p1 = __expf((sc[nj][1] - m2[0]) * SC_);
            float p2 = __expf((sc[nj][2] - m2[1]) * SC_);
            float p3 = __expf((sc[nj][3] - m2[1]) * SC_);
            rs[0] += p0 + p1;
            rs[1] += p2 + p3;
            __nv_bfloat162 h01, h23, l01, l23;
            h01.x = __float2bfloat16(p0); h01.y = __float2bfloat16(p1);
            l01.x = __float2bfloat16(p0 - __bfloat162float(h01.x));
            l01.y = __float2bfloat16(p1 - __bfloat162float(h01.y));
            h23.x = __float2bfloat16(p2); h23.y = __float2bfloat16(p3);
            l23.x = __float2bfloat16(p2 - __bfloat162float(h23.x));
            l23.y = __float2bfloat16(p3 - __bfloat162float(h23.y));
            ph[nj][0] = *(unsigned int*)&h01;
            ph[nj][1] = *(unsigned int*)&h23;
            pl[nj][0] = *(unsigned int*)&l01;
            pl[nj][1] = *(unsigned int*)&l23;
        }
#pragma unroll
        for (int off = 1; off <= 2; off <<= 1) {
            rs[0] += __shfl_xor_sync(0xffffffffu, rs[0], off);
            rs[1] += __shfl_xor_sync(0xffffffffu, rs[1], off);
        }
#pragma unroll
        for (int h = 0; h < 2; h++) l2[h] = l2[h]*corr[h] + rs[h];
#pragma unroll
        for (int nj = 0; nj < 8; nj++) {
            oc[nj][0] *= corr[0]; oc[nj][1] *= corr[0];
            oc[nj][2] *= corr[1]; oc[nj][3] *= corr[1];
        }

#pragma unroll
        for (int ks = 0; ks < 12; ks++) {
            int kk = ks & 3;
            unsigned int a0, a1, a2, a3;
            if (ks < 8) {
                a0 = ph[2*kk][0]; a1 = ph[2*kk][1];
                a2 = ph[2*kk+1][0]; a3 = ph[2*kk+1][1];
            } else {
                a0 = pl[2*kk][0]; a1 = pl[2*kk][1];
                a2 = pl[2*kk+1][0]; a3 = pl[2*kk+1][1];
            }
            int kcV = ((ks >= 4 && ks < 8) ? 64 : 0) + kk*16;
            int g = lane >> 3, rr = lane & 7;
#pragma unroll
            for (int njp = 0; njp < 4; njp++) {
                unsigned int addr = (unsigned int)__cvta_generic_to_shared(
                    &Vs[(kcV + rr + (g & 1)*8)*VST + njp*16 + (g >> 1)*8]);
                unsigned int b0, b1, b2, b3;
                asm volatile(
                    "ldmatrix.sync.aligned.m8n8.x4.trans.shared.b16 {%0,%1,%2,%3}, [%4];\n"
                    : "=r"(b0), "=r"(b1), "=r"(b2), "=r"(b3) : "r"(addr));
                MMA16816(oc[njp*2],   a0, a1, a2, a3, b0, b1);
                MMA16816(oc[njp*2+1], a0, a1, a2, a3, b2, b3);
            }
        }
    }

    int b = bh >> 4, h = bh & 15;
#pragma unroll
    for (int half = 0; half < 2; half++) {
        float inv = 1.0f / l2[half];
        int trow = qt*128 + wid*16 + lg + half*8;
        size_t rowbase = ((size_t)b*T_ + trow) * (size_t)KP_;
        int c0 = h*64 + lq*2;
#pragma unroll
        for (int nj = 0; nj < 8; nj++) {
            float y0 = oc[nj][half*2]   * inv;
            float y1 = oc[nj][half*2+1] * inv;
            __nv_bfloat162 hp, lp;
            hp.x = __float2bfloat16(y0);
            hp.y = __float2bfloat16(y1);
            lp.x = __float2bfloat16(y0 - __bfloat162float(hp.x));
            lp.y = __float2bfloat16(y1 - __bfloat162float(hp.y));
            int c = c0 + nj*8;
            *(__nv_bfloat162*)&g_ys[rowbase + c]        = hp;
            *(__nv_bfloat162*)&g_ys[rowbase + 1024 + c] = hp;
            *(__nv_bfloat162*)&g_ys[rowbase + 2048 + c] = lp;
        }
    }
}

// ---------------------------------------------------------------------------
extern "C" void kernel_launch(void* const* d_in, const int* in_sizes, int n_in,
                              void* d_out, int out_size)
{
    const float* x      = (const float*)d_in[0];
    const float* W_attn = (const float*)d_in[1];
    const float* b_attn = (const float*)d_in[2];
    const float* W_proj = (const float*)d_in[3];
    const float* b_proj = (const float*)d_in[4];
    float* out = (float*)d_out;

    split_x_kernel<<<(M_*C_/4 + 255)/256, 256>>>(x);
    split_w_kernel<<<(3*C_*C_/4 + 255)/256, 256>>>(W_attn);
    split_wp_kernel<<<(C_*C_/4 + 255)/256, 256>>>(W_proj);

    cudaFuncSetAttribute(mma_gemm<1>, cudaFuncAttributeMaxDynamicSharedMemorySize, GEMM_SMEM);
    cudaFuncSetAttribute(mma_gemm<0>, cudaFuncAttributeMaxDynamicSharedMemorySize, GEMM_SMEM);

    mma_gemm<1><<<dim3(3*C_/128, M_/256), 512, GEMM_SMEM>>>(b_attn, nullptr);

    rope_kernel<<<(B_*H_*T_*32)/256, 256>>>();

    cudaFuncSetAttribute(attn_mma, cudaFuncAttributeMaxDynamicSharedMemorySize, ATTN_SMEM);
    attn_mma<<<dim3(T_/128, B_*H_), 256, ATTN_SMEM>>>();

    mma_gemm<0><<<dim3(C_/128, M_/256), 512, GEMM_SMEM>>>(b_proj, out);
}

// round 13
// speedup vs baseline: 1.0720x; 1.0720x over previous
#include <cuda_runtime.h>
#include <cuda_bf16.h>
#include <math_constants.h>
#include <cstdint>

// Problem constants
#define B_  2
#define T_  2048
#define C_  1024
#define H_  16
#define D_  64
#define M_  (B_*T_)          // 4096 rows
#define BHTD (B_*H_*T_*D_)
#define KP_ (3*C_)           // 3072 split-K

// Scratch (device globals, referenced directly from kernels)
__device__ float g_q[BHTD];
__device__ float g_k[BHTD];
__device__ __nv_bfloat16 g_qs[(size_t)BHTD*2];       // q split [bh][t][hi64|lo64]
__device__ __nv_bfloat16 g_ks[(size_t)BHTD*2];       // k split
__device__ __nv_bfloat16 g_vs[(size_t)BHTD*2];       // v split
__device__ __nv_bfloat16 g_xs[(size_t)M_ * KP_];     // x split      [4096,3072]
__device__ __nv_bfloat16 g_ws[(size_t)3*C_ * KP_];   // W_attn split  [3072,3072]
__device__ __nv_bfloat16 g_ys[(size_t)M_ * KP_];     // y split       [4096,3072]
__device__ __nv_bfloat16 g_wps[(size_t)C_ * KP_];    // W_proj split  [1024,3072]

// ---------------------------------------------------------------------------
// fp32 -> bf16 hi/lo splits packed along K'=3K=3072.
// A-side: [hi, hi, lo];  B-side: [hi, lo, hi]  =>  hi*hi + hi*lo + lo*hi
// ---------------------------------------------------------------------------
__global__ void split_x_kernel(const float* __restrict__ src)
{
    int idx = blockIdx.x * blockDim.x + threadIdx.x;
    if (idx >= M_*C_/4) return;
    float4 v = ((const float4*)src)[idx];
    int r = idx >> 8;
    int k = (idx & 255) * 4;
    float vv[4] = {v.x, v.y, v.z, v.w};
    size_t base = (size_t)r * KP_ + k;
#pragma unroll
    for (int i = 0; i < 4; i++) {
        __nv_bfloat16 hi = __float2bfloat16(vv[i]);
        __nv_bfloat16 lo = __float2bfloat16(vv[i] - __bfloat162float(hi));
        g_xs[base + i]        = hi;
        g_xs[base + C_ + i]   = hi;
        g_xs[base + 2*C_ + i] = lo;
    }
}

__global__ void split_w_kernel(const float* __restrict__ src)
{
    int idx = blockIdx.x * blockDim.x + threadIdx.x;
    if (idx >= 3*C_*C_/4) return;
    float4 v = ((const float4*)src)[idx];
    int r = idx >> 8;
    int k = (idx & 255) * 4;
    float vv[4] = {v.x, v.y, v.z, v.w};
    size_t base = (size_t)r * KP_ + k;
#pragma unroll
    for (int i = 0; i < 4; i++) {
        __nv_bfloat16 hi = __float2bfloat16(vv[i]);
        __nv_bfloat16 lo = __float2bfloat16(vv[i] - __bfloat162float(hi));
        g_ws[base + i]        = hi;
        g_ws[base + C_ + i]   = lo;
        g_ws[base + 2*C_ + i] = hi;
    }
}

__global__ void split_wp_kernel(const float* __restrict__ src)
{
    int idx = blockIdx.x * blockDim.x + threadIdx.x;
    if (idx >= C_*C_/4) return;
    float4 v = ((const float4*)src)[idx];
    int r = idx >> 8;
    int k = (idx & 255) * 4;
    float vv[4] = {v.x, v.y, v.z, v.w};
    size_t base = (size_t)r * KP_ + k;
#pragma unroll
    for (int i = 0; i < 4; i++) {
        __nv_bfloat16 hi = __float2bfloat16(vv[i]);
        __nv_bfloat16 lo = __float2bfloat16(vv[i] - __bfloat162float(hi));
        g_wps[base + i]        = hi;
        g_wps[base + C_ + i]   = lo;
        g_wps[base + 2*C_ + i] = hi;
    }
}

// ---------------------------------------------------------------------------
// Shared PTX helpers
// ---------------------------------------------------------------------------
#define MMA16816(C4, A0,A1,A2,A3, B0,B1)                                      \
    asm volatile(                                                             \
        "mma.sync.aligned.m16n8k16.row.col.f32.bf16.bf16.f32 "                \
        "{%0,%1,%2,%3}, {%4,%5,%6,%7}, {%8,%9}, {%0,%1,%2,%3};\n"             \
        : "+f"((C4)[0]), "+f"((C4)[1]), "+f"((C4)[2]), "+f"((C4)[3])          \
        : "r"(A0), "r"(A1), "r"(A2), "r"(A3), "r"(B0), "r"(B1))

#define LDSM_X4(R0,R1,R2,R3, ptr)                                             \
    do {                                                                      \
        unsigned int _a = (unsigned int)__cvta_generic_to_shared(ptr);        \
        asm volatile(                                                         \
            "ldmatrix.sync.aligned.m8n8.x4.shared.b16 {%0,%1,%2,%3}, [%4];\n" \
            : "=r"(R0), "=r"(R1), "=r"(R2), "=r"(R3) : "r"(_a));              \
    } while (0)

#define CP_ASYNC16(smem_u32, gptr)                                            \
    asm volatile("cp.async.cg.shared.global [%0], [%1], 16;\n"                \
                 :: "r"(smem_u32), "l"(gptr))

// ---------------------------------------------------------------------------
// Tensor-core GEMM over pre-split operands (proven R9).
// 256x128 tile, 512 threads (16 warps: 8 M x 2 N, warp 32x64),
// 4-stage cp.async pipeline, ldmatrix.x4 fragments.
// MODE 1: g_xs * g_ws^T + b_attn -> q,k fp32 [B,H,T,D]; v split bf16 g_vs
// MODE 0: g_ys * g_wps^T + b_proj -> out row-major [M,1024]
// ---------------------------------------------------------------------------
#define SSTRIDE 40
#define GSTAGES 4
#define GEMM_SMEM ((GSTAGES*(256+128)*SSTRIDE)*2)

template<int MODE>
__global__ void __launch_bounds__(512) mma_gemm(
    const float* __restrict__ bias, float* __restrict__ out)
{
    const __nv_bfloat16* A  = (MODE == 1) ? g_xs : g_ys;
    const __nv_bfloat16* Bw = (MODE == 1) ? g_ws : g_wps;
    const int N = (MODE == 1) ? 3*C_ : C_;

    extern __shared__ __align__(16) __nv_bfloat16 gsm[];
    __nv_bfloat16* As = gsm;                          // [GSTAGES][256*SSTRIDE]
    __nv_bfloat16* Bs = gsm + GSTAGES*256*SSTRIDE;    // [GSTAGES][128*SSTRIDE]

    const int tid  = threadIdx.x;
    const int wid  = tid >> 5;
    const int lane = tid & 31;
    const int m0 = blockIdx.y * 256;
    const int n0 = blockIdx.x * 128;
    const int wm = (wid >> 1) * 32;
    const int wn = (wid & 1) * 64;
    const int lrow = lane & 15;
    const int lcol = (lane >> 4) << 3;

    const __nv_bfloat16* Ag = A  + (size_t)m0 * KP_;
    const __nv_bfloat16* Bg = Bw + (size_t)n0 * KP_;

    const int brow = tid >> 2, bseg = tid & 3;

    float c[2][8][4];
#pragma unroll
    for (int i = 0; i < 2; i++)
#pragma unroll
        for (int j = 0; j < 8; j++)
#pragma unroll
            for (int r = 0; r < 4; r++) c[i][j][r] = 0.f;

    const int nt = KP_ / 32;   // 96

#define ISSUE_STAGE(stage, k0)                                                \
    do {                                                                      \
        __nv_bfloat16* asb = As + (stage)*256*SSTRIDE;                        \
        __nv_bfloat16* bsb = Bs + (stage)*128*SSTRIDE;                        \
        _Pragma("unroll")                                                     \
        for (int i = 0; i < 2; i++) {                                         \
            int idx = tid + 512*i, row = idx >> 2, seg = idx & 3;             \
            unsigned int sa = (unsigned int)__cvta_generic_to_shared(         \
                &asb[row*SSTRIDE + seg*8]);                                   \
            CP_ASYNC16(sa, Ag + (size_t)row*KP_ + (k0) + seg*8);              \
        }                                                                     \
        {                                                                     \
            unsigned int sb = (unsigned int)__cvta_generic_to_shared(         \
                &bsb[brow*SSTRIDE + bseg*8]);                                 \
            CP_ASYNC16(sb, Bg + (size_t)brow*KP_ + (k0) + bseg*8);            \
        }                                                                     \
        asm volatile("cp.async.commit_group;\n");                             \
    } while (0)

    ISSUE_STAGE(0, 0);
    ISSUE_STAGE(1, 32);
    ISSUE_STAGE(2, 64);

    for (int kt = 0; kt < nt; kt++) {
        const int stage = kt % GSTAGES;
        asm volatile("cp.async.wait_group %0;\n" :: "n"(2));
        __syncthreads();

        if (kt + 3 < nt) {
            ISSUE_STAGE((kt + 3) % GSTAGES, (kt + 3) * 32);
        }

        const __nv_bfloat16* asb = As + stage*256*SSTRIDE;
        const __nv_bfloat16* bsb = Bs + stage*128*SSTRIDE;

#pragma unroll
        for (int ks = 0; ks < 2; ks++) {
            const int k16 = ks * 16;
            unsigned int af[2][4];
#pragma unroll
            for (int mi = 0; mi < 2; mi++) {
                LDSM_X4(af[mi][0], af[mi][1], af[mi][2], af[mi][3],
                        &asb[(wm + mi*16 + lrow)*SSTRIDE + k16 + lcol]);
            }
            unsigned int bm[4][4];
#pragma unroll
            for (int p = 0; p < 4; p++) {
                LDSM_X4(bm[p][0], bm[p][1], bm[p][2], bm[p][3],
                        &bsb[(wn + p*16 + lrow)*SSTRIDE + k16 + lcol]);
            }
#pragma unroll
            for (int mi = 0; mi < 2; mi++)
#pragma unroll
                for (int p = 0; p < 4; p++) {
                    MMA16816(c[mi][2*p],   af[mi][0], af[mi][1], af[mi][2], af[mi][3],
                             bm[p][0], bm[p][2]);
                    MMA16816(c[mi][2*p+1], af[mi][0], af[mi][1], af[mi][2], af[mi][3],
                             bm[p][1], bm[p][3]);
                }
        }
    }
#undef ISSUE_STAGE

#pragma unroll
    for (int mi = 0; mi < 2; mi++) {
#pragma unroll
        for (int nj = 0; nj < 8; nj++) {
            int row = m0 + wm + mi*16 + (lane >> 2);
            int col = n0 + wn + nj*8 + (lane & 3)*2;
            float b0 = bias[col], b1 = bias[col+1];
            float2 v0 = { c[mi][nj][0] + b0, c[mi][nj][1] + b1 };
            float2 v1 = { c[mi][nj][2] + b0, c[mi][nj][3] + b1 };
            if (MODE == 0) {
                *(float2*)&out[(size_t)row*N + col]     = v0;
                *(float2*)&out[(size_t)(row+8)*N + col] = v1;
            } else {
                int which = col >> 10;
                int h = (col & 1023) >> 6;
                int d = col & 63;
                int b = row >> 11, t = row & 2047;
                if (which == 2) {
                    size_t vb0 = ((size_t)(b*H_ + h)*T_ + t    )*128 + d;
                    size_t vb1 = ((size_t)(b*H_ + h)*T_ + t + 8)*128 + d;
                    __nv_bfloat162 h0, l0, h1, l1;
                    h0.x = __float2bfloat16(v0.x);
                    h0.y = __float2bfloat16(v0.y);
                    l0.x = __float2bfloat16(v0.x - __bfloat162float(h0.x));
                    l0.y = __float2bfloat16(v0.y - __bfloat162float(h0.y));
                    h1.x = __float2bfloat16(v1.x);
                    h1.y = __float2bfloat16(v1.y);
                    l1.x = __float2bfloat16(v1.x - __bfloat162float(h1.x));
                    l1.y = __float2bfloat16(v1.y - __bfloat162float(h1.y));
                    *(__nv_bfloat162*)&g_vs[vb0]      = h0;
                    *(__nv_bfloat162*)&g_vs[vb0 + 64] = l0;
                    *(__nv_bfloat162*)&g_vs[vb1]      = h1;
                    *(__nv_bfloat162*)&g_vs[vb1 + 64] = l1;
                } else {
                    float* dst = (which == 0) ? g_q : g_k;
                    size_t base0 = ((size_t)(b*H_ + h)*T_ + t    )*D_ + d;
                    size_t base1 = ((size_t)(b*H_ + h)*T_ + t + 8)*D_ + d;
                    *(float2*)&dst[base0] = v0;
                    *(float2*)&dst[base1] = v1;
                }
            }
        }
    }
}

// ---------------------------------------------------------------------------
// RoPE on q,k (fp32 in) -> split bf16 [hi64|lo64] rows out (g_qs, g_ks).
// ---------------------------------------------------------------------------
__global__ void rope_kernel()
{
    int idx = blockIdx.x * blockDim.x + threadIdx.x;
    int d  = idx & 31;
    int t  = (idx >> 5) & (T_ - 1);
    int bh = idx >> 16;
    size_t base = ((size_t)bh * T_ + t) * D_;
    size_t ob   = ((size_t)bh * T_ + t) * 128;

    const float L2_10000_OVER_32 = 13.287712379549449f / 32.0f;
    float f = exp2f(-(float)d * L2_10000_OVER_32);
    float ang = (float)t * f;
    float s, cc;
    sincosf(ang, &s, &cc);

    float q1 = g_q[base + d], q2 = g_q[base + d + 32];
    float o1 = q1*cc - q2*s;
    float o2 = q2*cc + q1*s;
    __nv_bfloat16 h1 = __float2bfloat16(o1);
    __nv_bfloat16 h2 = __float2bfloat16(o2);
    g_qs[ob + d]           = h1;
    g_qs[ob + d + 32]      = h2;
    g_qs[ob + 64 + d]      = __float2bfloat16(o1 - __bfloat162float(h1));
    g_qs[ob + 64 + d + 32] = __float2bfloat16(o2 - __bfloat162float(h2));

    float k1 = g_k[base + d], k2 = g_k[base + d + 32];
    o1 = k1*cc - k2*s;
    o2 = k2*cc + k1*s;
    h1 = __float2bfloat16(o1);
    h2 = __float2bfloat16(o2);
    g_ks[ob + d]           = h1;
    g_ks[ob + d + 32]      = h2;
    g_ks[ob + 64 + d]      = __float2bfloat16(o1 - __bfloat162float(h1));
    g_ks[ob + 64 + d + 32] = __float2bfloat16(o2 - __bfloat162float(h2));
}

// ---------------------------------------------------------------------------
// Tensor-core causal flash attention over pre-split bf16 q/k/v.
// NEW vs R9: K/V tiles double-buffered via cp.async — tile jt+1's global
// loads overlap tile jt's compute (removes exposed DRAM/L2 latency per tile).
// ---------------------------------------------------------------------------
#define QST 136
#define KST 136
#define VST 72
#define SC_ 0.125f
#define ATTN_SMEM ((128*QST + 2*64*KST + 2*128*VST) * 2)

__global__ void __launch_bounds__(256) attn_mma()
{
    extern __shared__ __align__(16) __nv_bfloat16 smA[];
    __nv_bfloat16* Qs = smA;                 // [128][QST]: [q_hi(64) | q_lo(64)]
    __nv_bfloat16* Ks = Qs + 128*QST;        // 2 x [64][KST]
    __nv_bfloat16* Vs = Ks + 2*64*KST;       // 2 x [128][VST] (hi rows 0-63, lo 64-127)

    const int qt  = (int)gridDim.x - 1 - (int)blockIdx.x;
    const int bh  = blockIdx.y;
    const int tid = threadIdx.x;
    const int wid = tid >> 5;
    const int lane = tid & 31;
    const int lg = lane >> 2;
    const int lq = lane & 3;
    const int lrow = lane & 15;
    const int lcol = (lane >> 4) << 3;

    const int jmax = 2*qt + 1;

    // prefetch tile 0 (cp.async), then load Q while it flies
#define ATTN_LOAD(jtv, bufv)                                                  \
    do {                                                                      \
        const __nv_bfloat16* ksrc = g_ks + ((size_t)bh*T_ + (jtv)*64)*128;    \
        const __nv_bfloat16* vsrc = g_vs + ((size_t)bh*T_ + (jtv)*64)*128;    \
        __nv_bfloat16* Kb = Ks + (bufv)*64*KST;                               \
        __nv_bfloat16* Vb = Vs + (bufv)*128*VST;                              \
        _Pragma("unroll")                                                     \
        for (int i = 0; i < 4; i++) {                                         \
            int idx = tid + i*256;                                            \
            int r = idx >> 4, u = idx & 15;                                   \
            unsigned int ka = (unsigned int)__cvta_generic_to_shared(         \
                &Kb[r*KST + u*8]);                                            \
            CP_ASYNC16(ka, &ksrc[r*128 + u*8]);                               \
            unsigned int va;                                                  \
            if (u < 8)                                                        \
                va = (unsigned int)__cvta_generic_to_shared(                  \
                    &Vb[r*VST + u*8]);                                        \
            else                                                              \
                va = (unsigned int)__cvta_generic_to_shared(                  \
                    &Vb[(r+64)*VST + (u-8)*8]);                               \
            CP_ASYNC16(va, &vsrc[r*128 + u*8]);                               \
        }                                                                     \
        asm volatile("cp.async.commit_group;\n");                             \
    } while (0)

    ATTN_LOAD(0, 0);

    const __nv_bfloat16* qsrc = g_qs + ((size_t)bh*T_ + qt*128)*128;
#pragma unroll
    for (int i = 0; i < 8; i++) {
        int idx = tid + i*256;
        int r = idx >> 4, u = (idx & 15) * 8;
        *(uint4*)&Qs[r*QST + u] = *(const uint4*)&qsrc[r*128 + u];
    }

    float m2[2] = {-CUDART_INF_F, -CUDART_INF_F};
    float l2[2] = {0.f, 0.f};
    float oc[8][4];
#pragma unroll
    for (int j = 0; j < 8; j++)
#pragma unroll
        for (int r = 0; r < 4; r++) oc[j][r] = 0.f;

    for (int jt = 0; jt <= jmax; jt++) {
        const int buf = jt & 1;
        // issue next tile into buf^1 (safe: last read in tile jt-1, sync'ed below)
        if (jt + 1 <= jmax) {
            ATTN_LOAD(jt + 1, buf ^ 1);
            asm volatile("cp.async.wait_group %0;\n" :: "n"(1));
        } else {
            asm volatile("cp.async.wait_group %0;\n" :: "n"(0));
        }
        __syncthreads();   // tile jt's data visible to all threads

        const __nv_bfloat16* Kb = Ks + buf*64*KST;
        const __nv_bfloat16* Vb = Vs + buf*128*VST;

        // ---- S = Q K^T (16x64 per warp, aliased hi/lo segments) ----
        float sc[8][4];
#pragma unroll
        for (int j = 0; j < 8; j++)
#pragma unroll
            for (int r = 0; r < 4; r++) sc[j][r] = 0.f;

#pragma unroll
        for (int ks = 0; ks < 12; ks++) {
            int kk16 = (ks & 3) * 16;
            int Aoff = (ks >= 8) ? 64 : 0;
            int Boff = (ks >= 4 && ks < 8) ? 64 : 0;
            unsigned int af[4];
            LDSM_X4(af[0], af[1], af[2], af[3],
                    &Qs[(wid*16 + lrow)*QST + Aoff + kk16 + lcol]);
#pragma unroll
            for (int p = 0; p < 4; p++) {
                unsigned int bm0, bm1, bm2, bm3;
                LDSM_X4(bm0, bm1, bm2, bm3,
                        &Kb[(p*16 + lrow)*KST + Boff + kk16 + lcol]);
                MMA16816(sc[2*p],   af[0], af[1], af[2], af[3], bm0, bm2);
                MMA16816(sc[2*p+1], af[0], af[1], af[2], af[3], bm1, bm3);
            }
        }

        // ---- mask + online softmax ----
        const bool needmask = (jt >= 2*qt);
        float rowm[2] = {-CUDART_INF_F, -CUDART_INF_F};
#pragma unroll
        for (int nj = 0; nj < 8; nj++) {
            if (needmask) {
                int kg  = jt*64 + nj*8 + lq*2;
                int qr0 = qt*128 + wid*16 + lg;
#pragma unroll
                for (int e = 0; e < 4; e++) {
                    if (kg + (e & 1) > qr0 + (e >> 1)*8) sc[nj][e] = -CUDART_INF_F;
                }
            }
            rowm[0] = fmaxf(rowm[0], fmaxf(sc[nj][0], sc[nj][1]));
            rowm[1] = fmaxf(rowm[1], fmaxf(sc[nj][2], sc[nj][3]));
        }
#pragma unroll
        for (int off = 1; off <= 2; off <<= 1) {
            rowm[0] = fmaxf(rowm[0], __shfl_xor_sync(0xffffffffu, rowm[0], off));
            rowm[1] = fmaxf(rowm[1], __shfl_xor_sync(0xffffffffu, rowm[1], off));
        }
        float corr[2];
#pragma unroll
        for (int h = 0; h < 2; h++) {
            float mn = fmaxf(m2[h], rowm[h]);
            corr[h] = __expf((m2[h] - mn) * SC_);
            m2[h] = mn;
        }
        float rs[2] = {0.f, 0.f};
        unsigned int ph[8][2], pl[8][2];
#pragma unroll
        for (int nj = 0; nj < 8; nj++) {
            float p0 = __expf((sc[nj][0] - m2[0]) * SC_);
            float p1 = __expf((sc[nj][1] - m2[0]) * SC_);
            float p2 = __expf((sc[nj][2] - m2[1]) * SC_);
            float p3 = __expf((sc[nj][3] - m2[1]) * SC_);
            rs[0] += p0 + p1;
            rs[1] += p2 + p3;
            __nv_bfloat162 h01, h23, l01, l23;
            h01.x = __float2bfloat16(p0); h01.y = __float2bfloat16(p1);
            l01.x = __float2bfloat16(p0 - __bfloat162float(h01.x));
            l01.y = __float2bfloat16(p1 - __bfloat162float(h01.y));
            h23.x = __float2bfloat16(p2); h23.y = __float2bfloat16(p3);
            l23.x = __float2bfloat16(p2 - __bfloat162float(h23.x));
            l23.y = __float2bfloat16(p3 - __bfloat162float(h23.y));
            ph[nj][0] = *(unsigned int*)&h01;
            ph[nj][1] = *(unsigned int*)&h23;
            pl[nj][0] = *(unsigned int*)&l01;
            pl[nj][1] = *(unsigned int*)&l23;
        }
#pragma unroll
        for (int off = 1; off <= 2; off <<= 1) {
            rs[0] += __shfl_xor_sync(0xffffffffu, rs[0], off);
            rs[1] += __shfl_xor_sync(0xffffffffu, rs[1], off);
        }
#pragma unroll
        for (int h = 0; h < 2; h++) l2[h] = l2[h]*corr[h] + rs[h];
#pragma unroll
        for (int nj = 0; nj < 8; nj++) {
            oc[nj][0] *= corr[0]; oc[nj][1] *= corr[0];
            oc[nj][2] *= corr[1]; oc[nj][3] *= corr[1];
        }

        // ---- O += P V ----
#pragma unroll
        for (int ks = 0; ks < 12; ks++) {
            int kk = ks & 3;
            unsigned int a0, a1, a2, a3;
            if (ks < 8) {
                a0 = ph[2*kk][0]; a1 = ph[2*kk][1];
                a2 = ph[2*kk+1][0]; a3 = ph[2*kk+1][1];
            } else {
                a0 = pl[2*kk][0]; a1 = pl[2*kk][1];
                a2 = pl[2*kk+1][0]; a3 = pl[2*kk+1][1];
            }
            int kcV = ((ks >= 4 && ks < 8) ? 64 : 0) + kk*16;
            int g = lane >> 3, rr = lane & 7;
#pragma unroll
            for (int njp = 0; njp < 4; njp++) {
                unsigned int addr = (unsigned int)__cvta_generic_to_shared(
                    &Vb[(kcV + rr + (g & 1)*8)*VST + njp*16 + (g >> 1)*8]);
                unsigned int b0, b1, b2, b3;
                asm volatile(
                    "ldmatrix.sync.aligned.m8n8.x4.trans.shared.b16 {%0,%1,%2,%3}, [%4];\n"
                    : "=r"(b0), "=r"(b1), "=r"(b2), "=r"(b3) : "r"(addr));
                MMA16816(oc[njp*2],   a0, a1, a2, a3, b0, b1);
                MMA16816(oc[njp*2+1], a0, a1, a2, a3, b2, b3);
            }
        }
        __syncthreads();   // all reads of buf done before next issue overwrites it
    }
#undef ATTN_LOAD

    int b = bh >> 4, h = bh & 15;
#pragma unroll
    for (int half = 0; half < 2; half++) {
        float inv = 1.0f / l2[half];
        int trow = qt*128 + wid*16 + lg + half*8;
        size_t rowbase = ((size_t)b*T_ + trow) * (size_t)KP_;
        int c0 = h*64 + lq*2;
#pragma unroll
        for (int nj = 0; nj < 8; nj++) {
            float y0 = oc[nj][half*2]   * inv;
            float y1 = oc[nj][half*2+1] * inv;
            __nv_bfloat162 hp, lp;
            hp.x = __float2bfloat16(y0);
            hp.y = __float2bfloat16(y1);
            lp.x = __float2bfloat16(y0 - __bfloat162float(hp.x));
            lp.y = __float2bfloat16(y1 - __bfloat162float(hp.y));
            int c = c0 + nj*8;
            *(__nv_bfloat162*)&g_ys[rowbase + c]        = hp;
            *(__nv_bfloat162*)&g_ys[rowbase + 1024 + c] = hp;
            *(__nv_bfloat162*)&g_ys[rowbase + 2048 + c] = lp;
        }
    }
}

// ---------------------------------------------------------------------------
extern "C" void kernel_launch(void* const* d_in, const int* in_sizes, int n_in,
                              void* d_out, int out_size)
{
    const float* x      = (const float*)d_in[0];
    const float* W_attn = (const float*)d_in[1];
    const float* b_attn = (const float*)d_in[2];
    const float* W_proj = (const float*)d_in[3];
    const float* b_proj = (const float*)d_in[4];
    float* out = (float*)d_out;

    split_x_kernel<<<(M_*C_/4 + 255)/256, 256>>>(x);
    split_w_kernel<<<(3*C_*C_/4 + 255)/256, 256>>>(W_attn);
    split_wp_kernel<<<(C_*C_/4 + 255)/256, 256>>>(W_proj);

    cudaFuncSetAttribute(mma_gemm<1>, cudaFuncAttributeMaxDynamicSharedMemorySize, GEMM_SMEM);
    cudaFuncSetAttribute(mma_gemm<0>, cudaFuncAttributeMaxDynamicSharedMemorySize, GEMM_SMEM);

    mma_gemm<1><<<dim3(3*C_/128, M_/256), 512, GEMM_SMEM>>>(b_attn, nullptr);

    rope_kernel<<<(B_*H_*T_*32)/256, 256>>>();

    cudaFuncSetAttribute(attn_mma, cudaFuncAttributeMaxDynamicSharedMemorySize, ATTN_SMEM);
    attn_mma<<<dim3(T_/128, B_*H_), 256, ATTN_SMEM>>>();

    mma_gemm<0><<<dim3(C_/128, M_/256), 512, GEMM_SMEM>>>(b_proj, out);
}

// round 14
// speedup vs baseline: 1.3711x; 1.2791x over previous
#include <cuda_runtime.h>
#include <cuda_bf16.h>
#include <cuda_fp16.h>
#include <math_constants.h>
#include <cstdint>

// Problem constants
#define B_  2
#define T_  2048
#define C_  1024
#define H_  16
#define D_  64
#define M_  (B_*T_)          // 4096 rows
#define BHTD (B_*H_*T_*D_)
#define KP2 2048             // fp16 two-term split K'

// Scratch (device globals, referenced directly from kernels)
__device__ float g_q[BHTD];
__device__ float g_k[BHTD];
__device__ __nv_bfloat16 g_qs[(size_t)BHTD*2];       // q split [bh][t][hi64|lo64] (bf16, attention)
__device__ __nv_bfloat16 g_ks[(size_t)BHTD*2];       // k split
__device__ __nv_bfloat16 g_vs[(size_t)BHTD*2];       // v split
__device__ __half g_xs[(size_t)M_ * KP2];            // x  fp16 [hi(1024)|lo(1024)]
__device__ __half g_ws[(size_t)3*C_ * C_];           // W_attn fp16 hi only
__device__ __half g_ys[(size_t)M_ * KP2];            // y  fp16 [hi|lo]
__device__ __half g_wps[(size_t)C_ * C_];            // W_proj fp16 hi only

// ---------------------------------------------------------------------------
// fp32 -> fp16 splits. A-side: [hi, lo]; B-side: hi only (segment reused).
// dot over K'' = (A_hi + A_lo) . B_hi  ~= A . B_hi ; error = A.B_lo ~ 2^-12
// ---------------------------------------------------------------------------
__global__ void split_x_kernel(const float* __restrict__ src)
{
    int idx = blockIdx.x * blockDim.x + threadIdx.x;
    if (idx >= M_*C_/4) return;
    float4 v = ((const float4*)src)[idx];
    int r = idx >> 8;
    int k = (idx & 255) * 4;
    float vv[4] = {v.x, v.y, v.z, v.w};
    size_t base = (size_t)r * KP2 + k;
#pragma unroll
    for (int i = 0; i < 4; i++) {
        __half hi = __float2half_rn(vv[i]);
        __half lo = __float2half_rn(vv[i] - __half2float(hi));
        g_xs[base + i]      = hi;
        g_xs[base + C_ + i] = lo;
    }
}

__global__ void split_w_kernel(const float* __restrict__ src)
{
    int idx = blockIdx.x * blockDim.x + threadIdx.x;
    if (idx >= 3*C_*C_/4) return;
    float4 v = ((const float4*)src)[idx];
    __half2 a, b;
    a.x = __float2half_rn(v.x); a.y = __float2half_rn(v.y);
    b.x = __float2half_rn(v.z); b.y = __float2half_rn(v.w);
    *(__half2*)&g_ws[(size_t)idx*4]     = a;
    *(__half2*)&g_ws[(size_t)idx*4 + 2] = b;
}

__global__ void split_wp_kernel(const float* __restrict__ src)
{
    int idx = blockIdx.x * blockDim.x + threadIdx.x;
    if (idx >= C_*C_/4) return;
    float4 v = ((const float4*)src)[idx];
    __half2 a, b;
    a.x = __float2half_rn(v.x); a.y = __float2half_rn(v.y);
    b.x = __float2half_rn(v.z); b.y = __float2half_rn(v.w);
    *(__half2*)&g_wps[(size_t)idx*4]     = a;
    *(__half2*)&g_wps[(size_t)idx*4 + 2] = b;
}

// ---------------------------------------------------------------------------
// Shared PTX helpers
// ---------------------------------------------------------------------------
#define MMA16816F16(C4, A0,A1,A2,A3, B0,B1)                                   \
    asm volatile(                                                             \
        "mma.sync.aligned.m16n8k16.row.col.f32.f16.f16.f32 "                  \
        "{%0,%1,%2,%3}, {%4,%5,%6,%7}, {%8,%9}, {%0,%1,%2,%3};\n"             \
        : "+f"((C4)[0]), "+f"((C4)[1]), "+f"((C4)[2]), "+f"((C4)[3])          \
        : "r"(A0), "r"(A1), "r"(A2), "r"(A3), "r"(B0), "r"(B1))

#define MMA16816(C4, A0,A1,A2,A3, B0,B1)                                      \
    asm volatile(                                                             \
        "mma.sync.aligned.m16n8k16.row.col.f32.bf16.bf16.f32 "                \
        "{%0,%1,%2,%3}, {%4,%5,%6,%7}, {%8,%9}, {%0,%1,%2,%3};\n"             \
        : "+f"((C4)[0]), "+f"((C4)[1]), "+f"((C4)[2]), "+f"((C4)[3])          \
        : "r"(A0), "r"(A1), "r"(A2), "r"(A3), "r"(B0), "r"(B1))

#define LDSM_X4(R0,R1,R2,R3, ptr)                                             \
    do {                                                                      \
        unsigned int _a = (unsigned int)__cvta_generic_to_shared(ptr);        \
        asm volatile(                                                         \
            "ldmatrix.sync.aligned.m8n8.x4.shared.b16 {%0,%1,%2,%3}, [%4];\n" \
            : "=r"(R0), "=r"(R1), "=r"(R2), "=r"(R3) : "r"(_a));              \
    } while (0)

#define CP_ASYNC16(smem_u32, gptr)                                            \
    asm volatile("cp.async.cg.shared.global [%0], [%1], 16;\n"                \
                 :: "r"(smem_u32), "l"(gptr))

// ---------------------------------------------------------------------------
// fp16 tensor-core GEMM, K''=2048 ([hi|lo] A x duplicated-hi B).
// 256x128 tile, 512 threads (16 warps: 8 M x 2 N, warp 32x64),
// 4-stage cp.async pipeline, ldmatrix.x4 fragments.
// B segment 1 duplicates segment 0 -> loader reads (k & 1023); W buffer is
// plain fp16(W) of size [N,1024].
// MODE 1: x*W_attn^T + b_attn -> q,k fp32 [B,H,T,D]; v split bf16 g_vs
// MODE 0: y*W_proj^T + b_proj -> out row-major [M,1024]
// ---------------------------------------------------------------------------
#define SSTRIDE 40
#define GSTAGES 4
#define GEMM_SMEM ((GSTAGES*(256+128)*SSTRIDE)*2)

template<int MODE>
__global__ void __launch_bounds__(512) mma_gemm(
    const float* __restrict__ bias, float* __restrict__ out)
{
    const __half* A  = (MODE == 1) ? g_xs : g_ys;
    const __half* Bw = (MODE == 1) ? g_ws : g_wps;
    const int N = (MODE == 1) ? 3*C_ : C_;

    extern __shared__ __align__(16) __half gsm[];
    __half* As = gsm;                          // [GSTAGES][256*SSTRIDE]
    __half* Bs = gsm + GSTAGES*256*SSTRIDE;    // [GSTAGES][128*SSTRIDE]

    const int tid  = threadIdx.x;
    const int wid  = tid >> 5;
    const int lane = tid & 31;
    const int m0 = blockIdx.y * 256;
    const int n0 = blockIdx.x * 128;
    const int wm = (wid >> 1) * 32;
    const int wn = (wid & 1) * 64;
    const int lrow = lane & 15;
    const int lcol = (lane >> 4) << 3;

    const __half* Ag = A  + (size_t)m0 * KP2;
    const __half* Bg = Bw + (size_t)n0 * C_;

    const int brow = tid >> 2, bseg = tid & 3;

    float c[2][8][4];
#pragma unroll
    for (int i = 0; i < 2; i++)
#pragma unroll
        for (int j = 0; j < 8; j++)
#pragma unroll
            for (int r = 0; r < 4; r++) c[i][j][r] = 0.f;

    const int nt = KP2 / 32;   // 64

#define ISSUE_STAGE(stage, k0)                                                \
    do {                                                                      \
        __half* asb = As + (stage)*256*SSTRIDE;                               \
        __half* bsb = Bs + (stage)*128*SSTRIDE;                               \
        _Pragma("unroll")                                                     \
        for (int i = 0; i < 2; i++) {                                         \
            int idx = tid + 512*i, row = idx >> 2, seg = idx & 3;             \
            unsigned int sa = (unsigned int)__cvta_generic_to_shared(         \
                &asb[row*SSTRIDE + seg*8]);                                   \
            CP_ASYNC16(sa, Ag + (size_t)row*KP2 + (k0) + seg*8);              \
        }                                                                     \
        {                                                                     \
            unsigned int sb = (unsigned int)__cvta_generic_to_shared(         \
                &bsb[brow*SSTRIDE + bseg*8]);                                 \
            CP_ASYNC16(sb, Bg + (size_t)brow*C_ + (((k0) & 1023) + bseg*8));  \
        }                                                                     \
        asm volatile("cp.async.commit_group;\n");                             \
    } while (0)

    ISSUE_STAGE(0, 0);
    ISSUE_STAGE(1, 32);
    ISSUE_STAGE(2, 64);

    for (int kt = 0; kt < nt; kt++) {
        const int stage = kt % GSTAGES;
        asm volatile("cp.async.wait_group %0;\n" :: "n"(2));
        __syncthreads();

        if (kt + 3 < nt) {
            ISSUE_STAGE((kt + 3) % GSTAGES, (kt + 3) * 32);
        }

        const __half* asb = As + stage*256*SSTRIDE;
        const __half* bsb = Bs + stage*128*SSTRIDE;

#pragma unroll
        for (int ks = 0; ks < 2; ks++) {
            const int k16 = ks * 16;
            unsigned int af[2][4];
#pragma unroll
            for (int mi = 0; mi < 2; mi++) {
                LDSM_X4(af[mi][0], af[mi][1], af[mi][2], af[mi][3],
                        &asb[(wm + mi*16 + lrow)*SSTRIDE + k16 + lcol]);
            }
            unsigned int bm[4][4];
#pragma unroll
            for (int p = 0; p < 4; p++) {
                LDSM_X4(bm[p][0], bm[p][1], bm[p][2], bm[p][3],
                        &bsb[(wn + p*16 + lrow)*SSTRIDE + k16 + lcol]);
            }
#pragma unroll
            for (int mi = 0; mi < 2; mi++)
#pragma unroll
                for (int p = 0; p < 4; p++) {
                    MMA16816F16(c[mi][2*p],   af[mi][0], af[mi][1], af[mi][2], af[mi][3],
                                bm[p][0], bm[p][2]);
                    MMA16816F16(c[mi][2*p+1], af[mi][0], af[mi][1], af[mi][2], af[mi][3],
                                bm[p][1], bm[p][3]);
                }
        }
    }
#undef ISSUE_STAGE

#pragma unroll
    for (int mi = 0; mi < 2; mi++) {
#pragma unroll
        for (int nj = 0; nj < 8; nj++) {
            int row = m0 + wm + mi*16 + (lane >> 2);
            int col = n0 + wn + nj*8 + (lane & 3)*2;
            float b0 = bias[col], b1 = bias[col+1];
            float2 v0 = { c[mi][nj][0] + b0, c[mi][nj][1] + b1 };
            float2 v1 = { c[mi][nj][2] + b0, c[mi][nj][3] + b1 };
            if (MODE == 0) {
                *(float2*)&out[(size_t)row*C_ + col]     = v0;
                *(float2*)&out[(size_t)(row+8)*C_ + col] = v1;
            } else {
                int which = col >> 10;
                int h = (col & 1023) >> 6;
                int d = col & 63;
                int b = row >> 11, t = row & 2047;
                if (which == 2) {
                    size_t vb0 = ((size_t)(b*H_ + h)*T_ + t    )*128 + d;
                    size_t vb1 = ((size_t)(b*H_ + h)*T_ + t + 8)*128 + d;
                    __nv_bfloat162 h0, l0, h1, l1;
                    h0.x = __float2bfloat16(v0.x);
                    h0.y = __float2bfloat16(v0.y);
                    l0.x = __float2bfloat16(v0.x - __bfloat162float(h0.x));
                    l0.y = __float2bfloat16(v0.y - __bfloat162float(h0.y));
                    h1.x = __float2bfloat16(v1.x);
                    h1.y = __float2bfloat16(v1.y);
                    l1.x = __float2bfloat16(v1.x - __bfloat162float(h1.x));
                    l1.y = __float2bfloat16(v1.y - __bfloat162float(h1.y));
                    *(__nv_bfloat162*)&g_vs[vb0]      = h0;
                    *(__nv_bfloat162*)&g_vs[vb0 + 64] = l0;
                    *(__nv_bfloat162*)&g_vs[vb1]      = h1;
                    *(__nv_bfloat162*)&g_vs[vb1 + 64] = l1;
                } else {
                    float* dst = (which == 0) ? g_q : g_k;
                    size_t base0 = ((size_t)(b*H_ + h)*T_ + t    )*D_ + d;
                    size_t base1 = ((size_t)(b*H_ + h)*T_ + t + 8)*D_ + d;
                    *(float2*)&dst[base0] = v0;
                    *(float2*)&dst[base1] = v1;
                }
            }
        }
    }
}

// ---------------------------------------------------------------------------
// RoPE on q,k (fp32 in) -> split bf16 [hi64|lo64] rows out (g_qs, g_ks).
// ---------------------------------------------------------------------------
__global__ void rope_kernel()
{
    int idx = blockIdx.x * blockDim.x + threadIdx.x;
    int d  = idx & 31;
    int t  = (idx >> 5) & (T_ - 1);
    int bh = idx >> 16;
    size_t base = ((size_t)bh * T_ + t) * D_;
    size_t ob   = ((size_t)bh * T_ + t) * 128;

    const float L2_10000_OVER_32 = 13.287712379549449f / 32.0f;
    float f = exp2f(-(float)d * L2_10000_OVER_32);
    float ang = (float)t * f;
    float s, cc;
    sincosf(ang, &s, &cc);

    float q1 = g_q[base + d], q2 = g_q[base + d + 32];
    float o1 = q1*cc - q2*s;
    float o2 = q2*cc + q1*s;
    __nv_bfloat16 h1 = __float2bfloat16(o1);
    __nv_bfloat16 h2 = __float2bfloat16(o2);
    g_qs[ob + d]           = h1;
    g_qs[ob + d + 32]      = h2;
    g_qs[ob + 64 + d]      = __float2bfloat16(o1 - __bfloat162float(h1));
    g_qs[ob + 64 + d + 32] = __float2bfloat16(o2 - __bfloat162float(h2));

    float k1 = g_k[base + d], k2 = g_k[base + d + 32];
    o1 = k1*cc - k2*s;
    o2 = k2*cc + k1*s;
    h1 = __float2bfloat16(o1);
    h2 = __float2bfloat16(o2);
    g_ks[ob + d]           = h1;
    g_ks[ob + d + 32]      = h2;
    g_ks[ob + 64 + d]      = __float2bfloat16(o1 - __bfloat162float(h1));
    g_ks[ob + 64 + d + 32] = __float2bfloat16(o2 - __bfloat162float(h2));
}

// ---------------------------------------------------------------------------
// Tensor-core causal flash attention over pre-split bf16 q/k/v (proven R13,
// cp.async double-buffered K/V). Epilogue writes y as fp16 [hi|lo] (K''=2048).
// ---------------------------------------------------------------------------
#define QST 136
#define KST 136
#define VST 72
#define SC_ 0.125f
#define ATTN_SMEM ((128*QST + 2*64*KST + 2*128*VST) * 2)

__global__ void __launch_bounds__(256) attn_mma()
{
    extern __shared__ __align__(16) __nv_bfloat16 smA[];
    __nv_bfloat16* Qs = smA;                 // [128][QST]: [q_hi(64) | q_lo(64)]
    __nv_bfloat16* Ks = Qs + 128*QST;        // 2 x [64][KST]
    __nv_bfloat16* Vs = Ks + 2*64*KST;       // 2 x [128][VST]

    const int qt  = (int)gridDim.x - 1 - (int)blockIdx.x;
    const int bh  = blockIdx.y;
    const int tid = threadIdx.x;
    const int wid = tid >> 5;
    const int lane = tid & 31;
    const int lg = lane >> 2;
    const int lq = lane & 3;
    const int lrow = lane & 15;
    const int lcol = (lane >> 4) << 3;

    const int jmax = 2*qt + 1;

#define ATTN_LOAD(jtv, bufv)                                                  \
    do {                                                                      \
        const __nv_bfloat16* ksrc = g_ks + ((size_t)bh*T_ + (jtv)*64)*128;    \
        const __nv_bfloat16* vsrc = g_vs + ((size_t)bh*T_ + (jtv)*64)*128;    \
        __nv_bfloat16* Kb = Ks + (bufv)*64*KST;                               \
        __nv_bfloat16* Vb = Vs + (bufv)*128*VST;                              \
        _Pragma("unroll")                                                     \
        for (int i = 0; i < 4; i++) {                                         \
            int idx = tid + i*256;                                            \
            int r = idx >> 4, u = idx & 15;                                   \
            unsigned int ka = (unsigned int)__cvta_generic_to_shared(         \
                &Kb[r*KST + u*8]);                                            \
            CP_ASYNC16(ka, &ksrc[r*128 + u*8]);                               \
            unsigned int va;                                                  \
            if (u < 8)                                                        \
                va = (unsigned int)__cvta_generic_to_shared(                  \
                    &Vb[r*VST + u*8]);                                        \
            else                                                              \
                va = (unsigned int)__cvta_generic_to_shared(                  \
                    &Vb[(r+64)*VST + (u-8)*8]);                               \
            CP_ASYNC16(va, &vsrc[r*128 + u*8]);                               \
        }                                                                     \
        asm volatile("cp.async.commit_group;\n");                             \
    } while (0)

    ATTN_LOAD(0, 0);

    const __nv_bfloat16* qsrc = g_qs + ((size_t)bh*T_ + qt*128)*128;
#pragma unroll
    for (int i = 0; i < 8; i++) {
        int idx = tid + i*256;
        int r = idx >> 4, u = (idx & 15) * 8;
        *(uint4*)&Qs[r*QST + u] = *(const uint4*)&qsrc[r*128 + u];
    }

    float m2[2] = {-CUDART_INF_F, -CUDART_INF_F};
    float l2[2] = {0.f, 0.f};
    float oc[8][4];
#pragma unroll
    for (int j = 0; j < 8; j++)
#pragma unroll
        for (int r = 0; r < 4; r++) oc[j][r] = 0.f;

    for (int jt = 0; jt <= jmax; jt++) {
        const int buf = jt & 1;
        if (jt + 1 <= jmax) {
            ATTN_LOAD(jt + 1, buf ^ 1);
            asm volatile("cp.async.wait_group %0;\n" :: "n"(1));
        } else {
            asm volatile("cp.async.wait_group %0;\n" :: "n"(0));
        }
        __syncthreads();

        const __nv_bfloat16* Kb = Ks + buf*64*KST;
        const __nv_bfloat16* Vb = Vs + buf*128*VST;

        float sc[8][4];
#pragma unroll
        for (int j = 0; j < 8; j++)
#pragma unroll
            for (int r = 0; r < 4; r++) sc[j][r] = 0.f;

#pragma unroll
        for (int ks = 0; ks < 12; ks++) {
            int kk16 = (ks & 3) * 16;
            int Aoff = (ks >= 8) ? 64 : 0;
            int Boff = (ks >= 4 && ks < 8) ? 64 : 0;
            unsigned int af[4];
            LDSM_X4(af[0], af[1], af[2], af[3],
                    &Qs[(wid*16 + lrow)*QST + Aoff + kk16 + lcol]);
#pragma unroll
            for (int p = 0; p < 4; p++) {
                unsigned int bm0, bm1, bm2, bm3;
                LDSM_X4(bm0, bm1, bm2, bm3,
                        &Kb[(p*16 + lrow)*KST + Boff + kk16 + lcol]);
                MMA16816(sc[2*p],   af[0], af[1], af[2], af[3], bm0, bm2);
                MMA16816(sc[2*p+1], af[0], af[1], af[2], af[3], bm1, bm3);
            }
        }

        const bool needmask = (jt >= 2*qt);
        float rowm[2] = {-CUDART_INF_F, -CUDART_INF_F};
#pragma unroll
        for (int nj = 0; nj < 8; nj++) {
            if (needmask) {
                int kg  = jt*64 + nj*8 + lq*2;
                int qr0 = qt*128 + wid*16 + lg;
#pragma unroll
                for (int e = 0; e < 4; e++) {
                    if (kg + (e & 1) > qr0 + (e >> 1)*8) sc[nj][e] = -CUDART_INF_F;
                }
            }
            rowm[0] = fmaxf(rowm[0], fmaxf(sc[nj][0], sc[nj][1]));
            rowm[1] = fmaxf(rowm[1], fmaxf(sc[nj][2], sc[nj][3]));
        }
#pragma unroll
        for (int off = 1; off <= 2; off <<= 1) {
            rowm[0] = fmaxf(rowm[0], __shfl_xor_sync(0xffffffffu, rowm[0], off));
            rowm[1] = fmaxf(rowm[1], __shfl_xor_sync(0xffffffffu, rowm[1], off));
        }
        float corr[2];
#pragma unroll
        for (int h = 0; h < 2; h++) {
            float mn = fmaxf(m2[h], rowm[h]);
            corr[h] = __expf((m2[h] - mn) * SC_);
            m2[h] = mn;
        }
        float rs[2] = {0.f, 0.f};
        unsigned int ph[8][2], pl[8][2];
#pragma unroll
        for (int nj = 0; nj < 8; nj++) {
            float p0 = __expf((sc[nj][0] - m2[0]) * SC_);
            float p1 = __expf((sc[nj][1] - m2[0]) * SC_);
            float p2 = __expf((sc[nj][2] - m2[1]) * SC_);
            float p3 = __expf((sc[nj][3] - m2[1]) * SC_);
            rs[0] += p0 + p1;
            rs[1] += p2 + p3;
            __nv_bfloat162 h01, h23, l01, l23;
            h01.x = __float2bfloat16(p0); h01.y = __float2bfloat16(p1);
            l01.x = __float2bfloat16(p0 - __bfloat162float(h01.x));
            l01.y = __float2bfloat16(p1 - __bfloat162float(h01.y));
            h23.x = __float2bfloat16(p2); h23.y = __float2bfloat16(p3);
            l23.x = __float2bfloat16(p2 - __bfloat162float(h23.x));
            l23.y = __float2bfloat16(p3 - __bfloat162float(h23.y));
            ph[nj][0] = *(unsigned int*)&h01;
            ph[nj][1] = *(unsigned int*)&h23;
            pl[nj][0] = *(unsigned int*)&l01;
            pl[nj][1] = *(unsigned int*)&l23;
        }
#pragma unroll
        for (int off = 1; off <= 2; off <<= 1) {
            rs[0] += __shfl_xor_sync(0xffffffffu, rs[0], off);
            rs[1] += __shfl_xor_sync(0xffffffffu, rs[1], off);
        }
#pragma unroll
        for (int h = 0; h < 2; h++) l2[h] = l2[h]*corr[h] + rs[h];
#pragma unroll
        for (int nj = 0; nj < 8; nj++) {
            oc[nj][0] *= corr[0]; oc[nj][1] *= corr[0];
            oc[nj][2] *= corr[1]; oc[nj][3] *= corr[1];
        }

#pragma unroll
        for (int ks = 0; ks < 12; ks++) {
            int kk = ks & 3;
            unsigned int a0, a1, a2, a3;
            if (ks < 8) {
                a0 = ph[2*kk][0]; a1 = ph[2*kk][1];
                a2 = ph[2*kk+1][0]; a3 = ph[2*kk+1][1];
            } else {
                a0 = pl[2*kk][0]; a1 = pl[2*kk][1];
                a2 = pl[2*kk+1][0]; a3 = pl[2*kk+1][1];
            }
            int kcV = ((ks >= 4 && ks < 8) ? 64 : 0) + kk*16;
            int g = lane >> 3, rr = lane & 7;
#pragma unroll
            for (int njp = 0; njp < 4; njp++) {
                unsigned int addr = (unsigned int)__cvta_generic_to_shared(
                    &Vb[(kcV + rr + (g & 1)*8)*VST + njp*16 + (g >> 1)*8]);
                unsigned int b0, b1, b2, b3;
                asm volatile(
                    "ldmatrix.sync.aligned.m8n8.x4.trans.shared.b16 {%0,%1,%2,%3}, [%4];\n"
                    : "=r"(b0), "=r"(b1), "=r"(b2), "=r"(b3) : "r"(addr));
                MMA16816(oc[njp*2],   a0, a1, a2, a3, b0, b1);
                MMA16816(oc[njp*2+1], a0, a1, a2, a3, b2, b3);
            }
        }
        __syncthreads();
    }
#undef ATTN_LOAD

    // epilogue: normalize, write fp16 [hi|lo] into g_ys (K''=2048)
    int b = bh >> 4, h = bh & 15;
#pragma unroll
    for (int half = 0; half < 2; half++) {
        float inv = 1.0f / l2[half];
        int trow = qt*128 + wid*16 + lg + half*8;
        size_t rowbase = ((size_t)b*T_ + trow) * (size_t)KP2;
        int c0 = h*64 + lq*2;
#pragma unroll
        for (int nj = 0; nj < 8; nj++) {
            float y0 = oc[nj][half*2]   * inv;
            float y1 = oc[nj][half*2+1] * inv;
            __half2 hp, lp;
            hp.x = __float2half_rn(y0);
            hp.y = __float2half_rn(y1);
            lp.x = __float2half_rn(y0 - __half2float(hp.x));
            lp.y = __float2half_rn(y1 - __half2float(hp.y));
            int c = c0 + nj*8;
            *(__half2*)&g_ys[rowbase + c]        = hp;
            *(__half2*)&g_ys[rowbase + 1024 + c] = lp;
        }
    }
}

// ---------------------------------------------------------------------------
extern "C" void kernel_launch(void* const* d_in, const int* in_sizes, int n_in,
                              void* d_out, int out_size)
{
    const float* x      = (const float*)d_in[0];
    const float* W_attn = (const float*)d_in[1];
    const float* b_attn = (const float*)d_in[2];
    const float* W_proj = (const float*)d_in[3];
    const float* b_proj = (const float*)d_in[4];
    float* out = (float*)d_out;

    split_x_kernel<<<(M_*C_/4 + 255)/256, 256>>>(x);
    split_w_kernel<<<(3*C_*C_/4 + 255)/256, 256>>>(W_attn);
    split_wp_kernel<<<(C_*C_/4 + 255)/256, 256>>>(W_proj);

    cudaFuncSetAttribute(mma_gemm<1>, cudaFuncAttributeMaxDynamicSharedMemorySize, GEMM_SMEM);
    cudaFuncSetAttribute(mma_gemm<0>, cudaFuncAttributeMaxDynamicSharedMemorySize, GEMM_SMEM);

    mma_gemm<1><<<dim3(3*C_/128, M_/256), 512, GEMM_SMEM>>>(b_attn, nullptr);

    rope_kernel<<<(B_*H_*T_*32)/256, 256>>>();

    cudaFuncSetAttribute(attn_mma, cudaFuncAttributeMaxDynamicSharedMemorySize, ATTN_SMEM);
    attn_mma<<<dim3(T_/128, B_*H_), 256, ATTN_SMEM>>>();

    mma_gemm<0><<<dim3(C_/128, M_/256), 512, GEMM_SMEM>>>(b_proj, out);
}

// round 15
// speedup vs baseline: 1.6027x; 1.1689x over previous
#include <cuda_runtime.h>
#include <cuda_bf16.h>
#include <cuda_fp16.h>
#include <math_constants.h>
#include <cstdint>

// Problem constants
#define B_  2
#define T_  2048
#define C_  1024
#define H_  16
#define D_  64
#define M_  (B_*T_)          // 4096 rows
#define BHTD (B_*H_*T_*D_)
#define KP2 2048             // fp16 two-term split K'

// Scratch (device globals, referenced directly from kernels)
__device__ float g_q[BHTD];
__device__ float g_k[BHTD];
__device__ __half g_qs[(size_t)BHTD*2];              // q fp16 [bh][t][hi64|lo64]
__device__ __half g_ks[(size_t)BHTD];                // k fp16 hi only [bh][t][64]
__device__ __half g_vs[(size_t)BHTD];                // v fp16 hi only [bh][t][64]
__device__ __half g_xs[(size_t)M_ * KP2];            // x  fp16 [hi(1024)|lo(1024)]
__device__ __half g_ws[(size_t)3*C_ * C_];           // W_attn fp16 hi only
__device__ __half g_ys[(size_t)M_ * KP2];            // y  fp16 [hi|lo]
__device__ __half g_wps[(size_t)C_ * C_];            // W_proj fp16 hi only

// ---------------------------------------------------------------------------
// fp32 -> fp16 splits. A-side: [hi, lo]; B-side: hi only (segment reused).
// ---------------------------------------------------------------------------
__global__ void split_x_kernel(const float* __restrict__ src)
{
    int idx = blockIdx.x * blockDim.x + threadIdx.x;
    if (idx >= M_*C_/4) return;
    float4 v = ((const float4*)src)[idx];
    int r = idx >> 8;
    int k = (idx & 255) * 4;
    float vv[4] = {v.x, v.y, v.z, v.w};
    size_t base = (size_t)r * KP2 + k;
#pragma unroll
    for (int i = 0; i < 4; i++) {
        __half hi = __float2half_rn(vv[i]);
        __half lo = __float2half_rn(vv[i] - __half2float(hi));
        g_xs[base + i]      = hi;
        g_xs[base + C_ + i] = lo;
    }
}

__global__ void split_w_kernel(const float* __restrict__ src)
{
    int idx = blockIdx.x * blockDim.x + threadIdx.x;
    if (idx >= 3*C_*C_/4) return;
    float4 v = ((const float4*)src)[idx];
    __half2 a, b;
    a.x = __float2half_rn(v.x); a.y = __float2half_rn(v.y);
    b.x = __float2half_rn(v.z); b.y = __float2half_rn(v.w);
    *(__half2*)&g_ws[(size_t)idx*4]     = a;
    *(__half2*)&g_ws[(size_t)idx*4 + 2] = b;
}

__global__ void split_wp_kernel(const float* __restrict__ src)
{
    int idx = blockIdx.x * blockDim.x + threadIdx.x;
    if (idx >= C_*C_/4) return;
    float4 v = ((const float4*)src)[idx];
    __half2 a, b;
    a.x = __float2half_rn(v.x); a.y = __float2half_rn(v.y);
    b.x = __float2half_rn(v.z); b.y = __float2half_rn(v.w);
    *(__half2*)&g_wps[(size_t)idx*4]     = a;
    *(__half2*)&g_wps[(size_t)idx*4 + 2] = b;
}

// ---------------------------------------------------------------------------
// Shared PTX helpers
// ---------------------------------------------------------------------------
#define MMA16816F16(C4, A0,A1,A2,A3, B0,B1)                                   \
    asm volatile(                                                             \
        "mma.sync.aligned.m16n8k16.row.col.f32.f16.f16.f32 "                  \
        "{%0,%1,%2,%3}, {%4,%5,%6,%7}, {%8,%9}, {%0,%1,%2,%3};\n"             \
        : "+f"((C4)[0]), "+f"((C4)[1]), "+f"((C4)[2]), "+f"((C4)[3])          \
        : "r"(A0), "r"(A1), "r"(A2), "r"(A3), "r"(B0), "r"(B1))

#define LDSM_X4(R0,R1,R2,R3, ptr)                                             \
    do {                                                                      \
        unsigned int _a = (unsigned int)__cvta_generic_to_shared(ptr);        \
        asm volatile(                                                         \
            "ldmatrix.sync.aligned.m8n8.x4.shared.b16 {%0,%1,%2,%3}, [%4];\n" \
            : "=r"(R0), "=r"(R1), "=r"(R2), "=r"(R3) : "r"(_a));              \
    } while (0)

#define CP_ASYNC16(smem_u32, gptr)                                            \
    asm volatile("cp.async.cg.shared.global [%0], [%1], 16;\n"                \
                 :: "r"(smem_u32), "l"(gptr))

// ---------------------------------------------------------------------------
// fp16 tensor-core GEMM, K''=2048 ([hi|lo] A x duplicated-hi B). Proven R14.
// MODE 1: x*W_attn^T + b_attn -> q,k fp32; v fp16 hi into g_vs
// MODE 0: y*W_proj^T + b_proj -> out row-major [M,1024]
// ---------------------------------------------------------------------------
#define SSTRIDE 40
#define GSTAGES 4
#define GEMM_SMEM ((GSTAGES*(256+128)*SSTRIDE)*2)

template<int MODE>
__global__ void __launch_bounds__(512) mma_gemm(
    const float* __restrict__ bias, float* __restrict__ out)
{
    const __half* A  = (MODE == 1) ? g_xs : g_ys;
    const __half* Bw = (MODE == 1) ? g_ws : g_wps;

    extern __shared__ __align__(16) __half gsm[];
    __half* As = gsm;                          // [GSTAGES][256*SSTRIDE]
    __half* Bs = gsm + GSTAGES*256*SSTRIDE;    // [GSTAGES][128*SSTRIDE]

    const int tid  = threadIdx.x;
    const int wid  = tid >> 5;
    const int lane = tid & 31;
    const int m0 = blockIdx.y * 256;
    const int n0 = blockIdx.x * 128;
    const int wm = (wid >> 1) * 32;
    const int wn = (wid & 1) * 64;
    const int lrow = lane & 15;
    const int lcol = (lane >> 4) << 3;

    const __half* Ag = A  + (size_t)m0 * KP2;
    const __half* Bg = Bw + (size_t)n0 * C_;

    const int brow = tid >> 2, bseg = tid & 3;

    float c[2][8][4];
#pragma unroll
    for (int i = 0; i < 2; i++)
#pragma unroll
        for (int j = 0; j < 8; j++)
#pragma unroll
            for (int r = 0; r < 4; r++) c[i][j][r] = 0.f;

    const int nt = KP2 / 32;   // 64

#define ISSUE_STAGE(stage, k0)                                                \
    do {                                                                      \
        __half* asb = As + (stage)*256*SSTRIDE;                               \
        __half* bsb = Bs + (stage)*128*SSTRIDE;                               \
        _Pragma("unroll")                                                     \
        for (int i = 0; i < 2; i++) {                                         \
            int idx = tid + 512*i, row = idx >> 2, seg = idx & 3;             \
            unsigned int sa = (unsigned int)__cvta_generic_to_shared(         \
                &asb[row*SSTRIDE + seg*8]);                                   \
            CP_ASYNC16(sa, Ag + (size_t)row*KP2 + (k0) + seg*8);              \
        }                                                                     \
        {                                                                     \
            unsigned int sb = (unsigned int)__cvta_generic_to_shared(         \
                &bsb[brow*SSTRIDE + bseg*8]);                                 \
            CP_ASYNC16(sb, Bg + (size_t)brow*C_ + (((k0) & 1023) + bseg*8));  \
        }                                                                     \
        asm volatile("cp.async.commit_group;\n");                             \
    } while (0)

    ISSUE_STAGE(0, 0);
    ISSUE_STAGE(1, 32);
    ISSUE_STAGE(2, 64);

    for (int kt = 0; kt < nt; kt++) {
        const int stage = kt % GSTAGES;
        asm volatile("cp.async.wait_group %0;\n" :: "n"(2));
        __syncthreads();

        if (kt + 3 < nt) {
            ISSUE_STAGE((kt + 3) % GSTAGES, (kt + 3) * 32);
        }

        const __half* asb = As + stage*256*SSTRIDE;
        const __half* bsb = Bs + stage*128*SSTRIDE;

#pragma unroll
        for (int ks = 0; ks < 2; ks++) {
            const int k16 = ks * 16;
            unsigned int af[2][4];
#pragma unroll
            for (int mi = 0; mi < 2; mi++) {
                LDSM_X4(af[mi][0], af[mi][1], af[mi][2], af[mi][3],
                        &asb[(wm + mi*16 + lrow)*SSTRIDE + k16 + lcol]);
            }
            unsigned int bm[4][4];
#pragma unroll
            for (int p = 0; p < 4; p++) {
                LDSM_X4(bm[p][0], bm[p][1], bm[p][2], bm[p][3],
                        &bsb[(wn + p*16 + lrow)*SSTRIDE + k16 + lcol]);
            }
#pragma unroll
            for (int mi = 0; mi < 2; mi++)
#pragma unroll
                for (int p = 0; p < 4; p++) {
                    MMA16816F16(c[mi][2*p],   af[mi][0], af[mi][1], af[mi][2], af[mi][3],
                                bm[p][0], bm[p][2]);
                    MMA16816F16(c[mi][2*p+1], af[mi][0], af[mi][1], af[mi][2], af[mi][3],
                                bm[p][1], bm[p][3]);
                }
        }
    }
#undef ISSUE_STAGE

#pragma unroll
    for (int mi = 0; mi < 2; mi++) {
#pragma unroll
        for (int nj = 0; nj < 8; nj++) {
            int row = m0 + wm + mi*16 + (lane >> 2);
            int col = n0 + wn + nj*8 + (lane & 3)*2;
            float b0 = bias[col], b1 = bias[col+1];
            float2 v0 = { c[mi][nj][0] + b0, c[mi][nj][1] + b1 };
            float2 v1 = { c[mi][nj][2] + b0, c[mi][nj][3] + b1 };
            if (MODE == 0) {
                *(float2*)&out[(size_t)row*C_ + col]     = v0;
                *(float2*)&out[(size_t)(row+8)*C_ + col] = v1;
            } else {
                int which = col >> 10;
                int h = (col & 1023) >> 6;
                int d = col & 63;
                int b = row >> 11, t = row & 2047;
                if (which == 2) {
                    // V: fp16 hi only
                    size_t vb0 = ((size_t)(b*H_ + h)*T_ + t    )*64 + d;
                    size_t vb1 = ((size_t)(b*H_ + h)*T_ + t + 8)*64 + d;
                    __half2 h0, h1;
                    h0.x = __float2half_rn(v0.x);
                    h0.y = __float2half_rn(v0.y);
                    h1.x = __float2half_rn(v1.x);
                    h1.y = __float2half_rn(v1.y);
                    *(__half2*)&g_vs[vb0] = h0;
                    *(__half2*)&g_vs[vb1] = h1;
                } else {
                    float* dst = (which == 0) ? g_q : g_k;
                    size_t base0 = ((size_t)(b*H_ + h)*T_ + t    )*D_ + d;
                    size_t base1 = ((size_t)(b*H_ + h)*T_ + t + 8)*D_ + d;
                    *(float2*)&dst[base0] = v0;
                    *(float2*)&dst[base1] = v1;
                }
            }
        }
    }
}

// ---------------------------------------------------------------------------
// RoPE on q,k (fp32 in) -> q fp16 [hi64|lo64] (g_qs), k fp16 hi only (g_ks).
// ---------------------------------------------------------------------------
__global__ void rope_kernel()
{
    int idx = blockIdx.x * blockDim.x + threadIdx.x;
    int d  = idx & 31;
    int t  = (idx >> 5) & (T_ - 1);
    int bh = idx >> 16;
    size_t base = ((size_t)bh * T_ + t) * D_;
    size_t oqb  = ((size_t)bh * T_ + t) * 128;
    size_t okb  = ((size_t)bh * T_ + t) * 64;

    const float L2_10000_OVER_32 = 13.287712379549449f / 32.0f;
    float f = exp2f(-(float)d * L2_10000_OVER_32);
    float ang = (float)t * f;
    float s, cc;
    sincosf(ang, &s, &cc);

    float q1 = g_q[base + d], q2 = g_q[base + d + 32];
    float o1 = q1*cc - q2*s;
    float o2 = q2*cc + q1*s;
    __half h1 = __float2half_rn(o1);
    __half h2 = __float2half_rn(o2);
    g_qs[oqb + d]           = h1;
    g_qs[oqb + d + 32]      = h2;
    g_qs[oqb + 64 + d]      = __float2half_rn(o1 - __half2float(h1));
    g_qs[oqb + 64 + d + 32] = __float2half_rn(o2 - __half2float(h2));

    float k1 = g_k[base + d], k2 = g_k[base + d + 32];
    o1 = k1*cc - k2*s;
    o2 = k2*cc + k1*s;
    g_ks[okb + d]      = __float2half_rn(o1);
    g_ks[okb + d + 32] = __float2half_rn(o2);
}

// ---------------------------------------------------------------------------
// fp16 tensor-core causal flash attention, two-term splits:
//   S = (q_hi + q_lo) . k_hi     (8 k16-steps)
//   O = (p_hi + p_lo) . v_hi     (8 k16-steps)
// K/V tiles hi-only (halved smem + traffic), cp.async double-buffered (R13).
// ---------------------------------------------------------------------------
#define QST 136
#define KST 72
#define VST 72
#define SC_ 0.125f
#define ATTN_SMEM ((128*QST + 2*64*KST + 2*64*VST) * 2)

__global__ void __launch_bounds__(256) attn_mma()
{
    extern __shared__ __align__(16) __half smA[];
    __half* Qs = smA;                 // [128][QST]: [q_hi(64) | q_lo(64)]
    __half* Ks = Qs + 128*QST;        // 2 x [64][KST] hi only
    __half* Vs = Ks + 2*64*KST;       // 2 x [64][VST] hi only

    const int qt  = (int)gridDim.x - 1 - (int)blockIdx.x;
    const int bh  = blockIdx.y;
    const int tid = threadIdx.x;
    const int wid = tid >> 5;
    const int lane = tid & 31;
    const int lg = lane >> 2;
    const int lq = lane & 3;
    const int lrow = lane & 15;
    const int lcol = (lane >> 4) << 3;

    const int jmax = 2*qt + 1;

#define ATTN_LOAD(jtv, bufv)                                                  \
    do {                                                                      \
        const __half* ksrc = g_ks + ((size_t)bh*T_ + (jtv)*64)*64;            \
        const __half* vsrc = g_vs + ((size_t)bh*T_ + (jtv)*64)*64;            \
        __half* Kb = Ks + (bufv)*64*KST;                                      \
        __half* Vb = Vs + (bufv)*64*VST;                                      \
        _Pragma("unroll")                                                     \
        for (int i = 0; i < 2; i++) {                                         \
            int idx = tid + i*256;                                            \
            int r = idx >> 3, u = idx & 7;                                    \
            unsigned int ka = (unsigned int)__cvta_generic_to_shared(         \
                &Kb[r*KST + u*8]);                                            \
            CP_ASYNC16(ka, &ksrc[r*64 + u*8]);                                \
            unsigned int va = (unsigned int)__cvta_generic_to_shared(         \
                &Vb[r*VST + u*8]);                                            \
            CP_ASYNC16(va, &vsrc[r*64 + u*8]);                                \
        }                                                                     \
        asm volatile("cp.async.commit_group;\n");                             \
    } while (0)

    ATTN_LOAD(0, 0);

    const __half* qsrc = g_qs + ((size_t)bh*T_ + qt*128)*128;
#pragma unroll
    for (int i = 0; i < 8; i++) {
        int idx = tid + i*256;
        int r = idx >> 4, u = (idx & 15) * 8;
        *(uint4*)&Qs[r*QST + u] = *(const uint4*)&qsrc[r*128 + u];
    }

    float m2[2] = {-CUDART_INF_F, -CUDART_INF_F};
    float l2[2] = {0.f, 0.f};
    float oc[8][4];
#pragma unroll
    for (int j = 0; j < 8; j++)
#pragma unroll
        for (int r = 0; r < 4; r++) oc[j][r] = 0.f;

    for (int jt = 0; jt <= jmax; jt++) {
        const int buf = jt & 1;
        if (jt + 1 <= jmax) {
            ATTN_LOAD(jt + 1, buf ^ 1);
            asm volatile("cp.async.wait_group %0;\n" :: "n"(1));
        } else {
            asm volatile("cp.async.wait_group %0;\n" :: "n"(0));
        }
        __syncthreads();

        const __half* Kb = Ks + buf*64*KST;
        const __half* Vb = Vs + buf*64*VST;

        // ---- S = (q_hi + q_lo) . k_hi ----
        float sc[8][4];
#pragma unroll
        for (int j = 0; j < 8; j++)
#pragma unroll
            for (int r = 0; r < 4; r++) sc[j][r] = 0.f;

#pragma unroll
        for (int ks = 0; ks < 8; ks++) {
            int kk16 = (ks & 3) * 16;
            int Aoff = (ks >= 4) ? 64 : 0;        // Q: [hi | lo]
            unsigned int af[4];
            LDSM_X4(af[0], af[1], af[2], af[3],
                    &Qs[(wid*16 + lrow)*QST + Aoff + kk16 + lcol]);
#pragma unroll
            for (int p = 0; p < 4; p++) {
                unsigned int bm0, bm1, bm2, bm3;
                LDSM_X4(bm0, bm1, bm2, bm3,
                        &Kb[(p*16 + lrow)*KST + kk16 + lcol]);
                MMA16816F16(sc[2*p],   af[0], af[1], af[2], af[3], bm0, bm2);
                MMA16816F16(sc[2*p+1], af[0], af[1], af[2], af[3], bm1, bm3);
            }
        }

        // ---- mask + online softmax ----
        const bool needmask = (jt >= 2*qt);
        float rowm[2] = {-CUDART_INF_F, -CUDART_INF_F};
#pragma unroll
        for (int nj = 0; nj < 8; nj++) {
            if (needmask) {
                int kg  = jt*64 + nj*8 + lq*2;
                int qr0 = qt*128 + wid*16 + lg;
#pragma unroll
                for (int e = 0; e < 4; e++) {
                    if (kg + (e & 1) > qr0 + (e >> 1)*8) sc[nj][e] = -CUDART_INF_F;
                }
            }
            rowm[0] = fmaxf(rowm[0], fmaxf(sc[nj][0], sc[nj][1]));
            rowm[1] = fmaxf(rowm[1], fmaxf(sc[nj][2], sc[nj][3]));
        }
#pragma unroll
        for (int off = 1; off <= 2; off <<= 1) {
            rowm[0] = fmaxf(rowm[0], __shfl_xor_sync(0xffffffffu, rowm[0], off));
            rowm[1] = fmaxf(rowm[1], __shfl_xor_sync(0xffffffffu, rowm[1], off));
        }
        float corr[2];
#pragma unroll
        for (int h = 0; h < 2; h++) {
            float mn = fmaxf(m2[h], rowm[h]);
            corr[h] = __expf((m2[h] - mn) * SC_);
            m2[h] = mn;
        }
        float rs[2] = {0.f, 0.f};
        unsigned int ph[8][2], pl[8][2];
#pragma unroll
        for (int nj = 0; nj < 8; nj++) {
            float p0 = __expf((sc[nj][0] - m2[0]) * SC_);
            float p1 = __expf((sc[nj][1] - m2[0]) * SC_);
            float p2 = __expf((sc[nj][2] - m2[1]) * SC_);
            float p3 = __expf((sc[nj][3] - m2[1]) * SC_);
            rs[0] += p0 + p1;
            rs[1] += p2 + p3;
            __half2 h01, h23, l01, l23;
            h01.x = __float2half_rn(p0); h01.y = __float2half_rn(p1);
            l01.x = __float2half_rn(p0 - __half2float(h01.x));
            l01.y = __float2half_rn(p1 - __half2float(h01.y));
            h23.x = __float2half_rn(p2); h23.y = __float2half_rn(p3);
            l23.x = __float2half_rn(p2 - __half2float(h23.x));
            l23.y = __float2half_rn(p3 - __half2float(h23.y));
            ph[nj][0] = *(unsigned int*)&h01;
            ph[nj][1] = *(unsigned int*)&h23;
            pl[nj][0] = *(unsigned int*)&l01;
            pl[nj][1] = *(unsigned int*)&l23;
        }
#pragma unroll
        for (int off = 1; off <= 2; off <<= 1) {
            rs[0] += __shfl_xor_sync(0xffffffffu, rs[0], off);
            rs[1] += __shfl_xor_sync(0xffffffffu, rs[1], off);
        }
#pragma unroll
        for (int h = 0; h < 2; h++) l2[h] = l2[h]*corr[h] + rs[h];
#pragma unroll
        for (int nj = 0; nj < 8; nj++) {
            oc[nj][0] *= corr[0]; oc[nj][1] *= corr[0];
            oc[nj][2] *= corr[1]; oc[nj][3] *= corr[1];
        }

        // ---- O += (p_hi + p_lo) . v_hi ----
#pragma unroll
        for (int ks = 0; ks < 8; ks++) {
            int kk = ks & 3;
            unsigned int a0, a1, a2, a3;
            if (ks < 4) {
                a0 = ph[2*kk][0]; a1 = ph[2*kk][1];
                a2 = ph[2*kk+1][0]; a3 = ph[2*kk+1][1];
            } else {
                a0 = pl[2*kk][0]; a1 = pl[2*kk][1];
                a2 = pl[2*kk+1][0]; a3 = pl[2*kk+1][1];
            }
            int kcV = kk*16;
            int g = lane >> 3, rr = lane & 7;
#pragma unroll
            for (int njp = 0; njp < 4; njp++) {
                unsigned int addr = (unsigned int)__cvta_generic_to_shared(
                    &Vb[(kcV + rr + (g & 1)*8)*VST + njp*16 + (g >> 1)*8]);
                unsigned int b0, b1, b2, b3;
                asm volatile(
                    "ldmatrix.sync.aligned.m8n8.x4.trans.shared.b16 {%0,%1,%2,%3}, [%4];\n"
                    : "=r"(b0), "=r"(b1), "=r"(b2), "=r"(b3) : "r"(addr));
                MMA16816F16(oc[njp*2],   a0, a1, a2, a3, b0, b1);
                MMA16816F16(oc[njp*2+1], a0, a1, a2, a3, b2, b3);
            }
        }
        __syncthreads();
    }
#undef ATTN_LOAD

    // epilogue: normalize, write fp16 [hi|lo] into g_ys (K''=2048)
    int b = bh >> 4, h = bh & 15;
#pragma unroll
    for (int half = 0; half < 2; half++) {
        float inv = 1.0f / l2[half];
        int trow = qt*128 + wid*16 + lg + half*8;
        size_t rowbase = ((size_t)b*T_ + trow) * (size_t)KP2;
        int c0 = h*64 + lq*2;
#pragma unroll
        for (int nj = 0; nj < 8; nj++) {
            float y0 = oc[nj][half*2]   * inv;
            float y1 = oc[nj][half*2+1] * inv;
            __half2 hp, lp;
            hp.x = __float2half_rn(y0);
            hp.y = __float2half_rn(y1);
            lp.x = __float2half_rn(y0 - __half2float(hp.x));
            lp.y = __float2half_rn(y1 - __half2float(hp.y));
            int c = c0 + nj*8;
            *(__half2*)&g_ys[rowbase + c]        = hp;
            *(__half2*)&g_ys[rowbase + 1024 + c] = lp;
        }
    }
}

// ---------------------------------------------------------------------------
extern "C" void kernel_launch(void* const* d_in, const int* in_sizes, int n_in,
                              void* d_out, int out_size)
{
    const float* x      = (const float*)d_in[0];
    const float* W_attn = (const float*)d_in[1];
    const float* b_attn = (const float*)d_in[2];
    const float* W_proj = (const float*)d_in[3];
    const float* b_proj = (const float*)d_in[4];
    float* out = (float*)d_out;

    split_x_kernel<<<(M_*C_/4 + 255)/256, 256>>>(x);
    split_w_kernel<<<(3*C_*C_/4 + 255)/256, 256>>>(W_attn);
    split_wp_kernel<<<(C_*C_/4 + 255)/256, 256>>>(W_proj);

    cudaFuncSetAttribute(mma_gemm<1>, cudaFuncAttributeMaxDynamicSharedMemorySize, GEMM_SMEM);
    cudaFuncSetAttribute(mma_gemm<0>, cudaFuncAttributeMaxDynamicSharedMemorySize, GEMM_SMEM);

    mma_gemm<1><<<dim3(3*C_/128, M_/256), 512, GEMM_SMEM>>>(b_attn, nullptr);

    rope_kernel<<<(B_*H_*T_*32)/256, 256>>>();

    cudaFuncSetAttribute(attn_mma, cudaFuncAttributeMaxDynamicSharedMemorySize, ATTN_SMEM);
    attn_mma<<<dim3(T_/128, B_*H_), 256, ATTN_SMEM>>>();

    mma_gemm<0><<<dim3(C_/128, M_/256), 512, GEMM_SMEM>>>(b_proj, out);
}

// round 16
// speedup vs baseline: 2.0105x; 1.2545x over previous
#include <cuda_runtime.h>
#include <cuda_bf16.h>
#include <cuda_fp16.h>
#include <math_constants.h>
#include <cstdint>

// Problem constants
#define B_  2
#define T_  2048
#define C_  1024
#define H_  16
#define D_  64
#define M_  (B_*T_)          // 4096 rows
#define BHTD (B_*H_*T_*D_)
#define KP2 2048             // fp16 two-term split K' (proj only)

// Scratch (device globals, referenced directly from kernels)
__device__ float g_q[BHTD];
__device__ float g_k[BHTD];
__device__ __half g_qs[(size_t)BHTD*2];              // q fp16 [bh][t][hi64|lo64]
__device__ __half g_ks[(size_t)BHTD];                // k fp16 hi only [bh][t][64]
__device__ __half g_vs[(size_t)BHTD];                // v fp16 hi only [bh][t][64]
__device__ __half g_xs[(size_t)M_ * C_];             // x fp16 hi only [4096,1024]
__device__ __half g_ws[(size_t)3*C_ * C_];           // W_attn fp16 hi only
__device__ __half g_ys[(size_t)M_ * KP2];            // y fp16 [hi|lo]
__device__ __half g_wps[(size_t)C_ * C_];            // W_proj fp16 hi only

// ---------------------------------------------------------------------------
// fp32 -> fp16 conversions.
// ---------------------------------------------------------------------------
__global__ void split_x_kernel(const float* __restrict__ src)
{
    int idx = blockIdx.x * blockDim.x + threadIdx.x;
    if (idx >= M_*C_/4) return;
    float4 v = ((const float4*)src)[idx];
    __half2 a, b;
    a.x = __float2half_rn(v.x); a.y = __float2half_rn(v.y);
    b.x = __float2half_rn(v.z); b.y = __float2half_rn(v.w);
    *(__half2*)&g_xs[(size_t)idx*4]     = a;
    *(__half2*)&g_xs[(size_t)idx*4 + 2] = b;
}

__global__ void split_w_kernel(const float* __restrict__ src)
{
    int idx = blockIdx.x * blockDim.x + threadIdx.x;
    if (idx >= 3*C_*C_/4) return;
    float4 v = ((const float4*)src)[idx];
    __half2 a, b;
    a.x = __float2half_rn(v.x); a.y = __float2half_rn(v.y);
    b.x = __float2half_rn(v.z); b.y = __float2half_rn(v.w);
    *(__half2*)&g_ws[(size_t)idx*4]     = a;
    *(__half2*)&g_ws[(size_t)idx*4 + 2] = b;
}

__global__ void split_wp_kernel(const float* __restrict__ src)
{
    int idx = blockIdx.x * blockDim.x + threadIdx.x;
    if (idx >= C_*C_/4) return;
    float4 v = ((const float4*)src)[idx];
    __half2 a, b;
    a.x = __float2half_rn(v.x); a.y = __float2half_rn(v.y);
    b.x = __float2half_rn(v.z); b.y = __float2half_rn(v.w);
    *(__half2*)&g_wps[(size_t)idx*4]     = a;
    *(__half2*)&g_wps[(size_t)idx*4 + 2] = b;
}

// ---------------------------------------------------------------------------
// Shared PTX helpers
// ---------------------------------------------------------------------------
#define MMA16816F16(C4, A0,A1,A2,A3, B0,B1)                                   \
    asm volatile(                                                             \
        "mma.sync.aligned.m16n8k16.row.col.f32.f16.f16.f32 "                  \
        "{%0,%1,%2,%3}, {%4,%5,%6,%7}, {%8,%9}, {%0,%1,%2,%3};\n"             \
        : "+f"((C4)[0]), "+f"((C4)[1]), "+f"((C4)[2]), "+f"((C4)[3])          \
        : "r"(A0), "r"(A1), "r"(A2), "r"(A3), "r"(B0), "r"(B1))

#define LDSM_X4(R0,R1,R2,R3, ptr)                                             \
    do {                                                                      \
        unsigned int _a = (unsigned int)__cvta_generic_to_shared(ptr);        \
        asm volatile(                                                         \
            "ldmatrix.sync.aligned.m8n8.x4.shared.b16 {%0,%1,%2,%3}, [%4];\n" \
            : "=r"(R0), "=r"(R1), "=r"(R2), "=r"(R3) : "r"(_a));              \
    } while (0)

#define CP_ASYNC16(smem_u32, gptr)                                            \
    asm volatile("cp.async.cg.shared.global [%0], [%1], 16;\n"                \
                 :: "r"(smem_u32), "l"(gptr))

// ---------------------------------------------------------------------------
// fp16 tensor-core GEMM (proven R14/R15 template).
// MODE 1: K=1024 plain fp16 (x hi-only): x*W_attn^T + b_attn
//         -> q,k fp32 [B,H,T,D]; v fp16 hi into g_vs
// MODE 0: K''=2048 two-term A ([hi|lo]) x dup-hi B: y*W_proj^T + b_proj -> out
// ---------------------------------------------------------------------------
#define SSTRIDE 40
#define GSTAGES 4
#define GEMM_SMEM ((GSTAGES*(256+128)*SSTRIDE)*2)

template<int MODE>
__global__ void __launch_bounds__(512) mma_gemm(
    const float* __restrict__ bias, float* __restrict__ out)
{
    const __half* A  = (MODE == 1) ? g_xs : g_ys;
    const __half* Bw = (MODE == 1) ? g_ws : g_wps;
    const int AK = (MODE == 1) ? C_ : KP2;     // A row stride / K''

    extern __shared__ __align__(16) __half gsm[];
    __half* As = gsm;                          // [GSTAGES][256*SSTRIDE]
    __half* Bs = gsm + GSTAGES*256*SSTRIDE;    // [GSTAGES][128*SSTRIDE]

    const int tid  = threadIdx.x;
    const int wid  = tid >> 5;
    const int lane = tid & 31;
    const int m0 = blockIdx.y * 256;
    const int n0 = blockIdx.x * 128;
    const int wm = (wid >> 1) * 32;
    const int wn = (wid & 1) * 64;
    const int lrow = lane & 15;
    const int lcol = (lane >> 4) << 3;

    const __half* Ag = A  + (size_t)m0 * AK;
    const __half* Bg = Bw + (size_t)n0 * C_;

    const int brow = tid >> 2, bseg = tid & 3;

    float c[2][8][4];
#pragma unroll
    for (int i = 0; i < 2; i++)
#pragma unroll
        for (int j = 0; j < 8; j++)
#pragma unroll
            for (int r = 0; r < 4; r++) c[i][j][r] = 0.f;

    const int nt = AK / 32;   // 32 (MODE 1) or 64 (MODE 0)

#define ISSUE_STAGE(stage, k0)                                                \
    do {                                                                      \
        __half* asb = As + (stage)*256*SSTRIDE;                               \
        __half* bsb = Bs + (stage)*128*SSTRIDE;                               \
        _Pragma("unroll")                                                     \
        for (int i = 0; i < 2; i++) {                                         \
            int idx = tid + 512*i, row = idx >> 2, seg = idx & 3;             \
            unsigned int sa = (unsigned int)__cvta_generic_to_shared(         \
                &asb[row*SSTRIDE + seg*8]);                                   \
            CP_ASYNC16(sa, Ag + (size_t)row*AK + (k0) + seg*8);               \
        }                                                                     \
        {                                                                     \
            unsigned int sb = (unsigned int)__cvta_generic_to_shared(         \
                &bsb[brow*SSTRIDE + bseg*8]);                                 \
            CP_ASYNC16(sb, Bg + (size_t)brow*C_ + (((k0) & 1023) + bseg*8));  \
        }                                                                     \
        asm volatile("cp.async.commit_group;\n");                             \
    } while (0)

    ISSUE_STAGE(0, 0);
    ISSUE_STAGE(1, 32);
    ISSUE_STAGE(2, 64);

    for (int kt = 0; kt < nt; kt++) {
        const int stage = kt % GSTAGES;
        asm volatile("cp.async.wait_group %0;\n" :: "n"(2));
        __syncthreads();

        if (kt + 3 < nt) {
            ISSUE_STAGE((kt + 3) % GSTAGES, (kt + 3) * 32);
        }

        const __half* asb = As + stage*256*SSTRIDE;
        const __half* bsb = Bs + stage*128*SSTRIDE;

#pragma unroll
        for (int ks = 0; ks < 2; ks++) {
            const int k16 = ks * 16;
            unsigned int af[2][4];
#pragma unroll
            for (int mi = 0; mi < 2; mi++) {
                LDSM_X4(af[mi][0], af[mi][1], af[mi][2], af[mi][3],
                        &asb[(wm + mi*16 + lrow)*SSTRIDE + k16 + lcol]);
            }
            unsigned int bm[4][4];
#pragma unroll
            for (int p = 0; p < 4; p++) {
                LDSM_X4(bm[p][0], bm[p][1], bm[p][2], bm[p][3],
                        &bsb[(wn + p*16 + lrow)*SSTRIDE + k16 + lcol]);
            }
#pragma unroll
            for (int mi = 0; mi < 2; mi++)
#pragma unroll
                for (int p = 0; p < 4; p++) {
                    MMA16816F16(c[mi][2*p],   af[mi][0], af[mi][1], af[mi][2], af[mi][3],
                                bm[p][0], bm[p][2]);
                    MMA16816F16(c[mi][2*p+1], af[mi][0], af[mi][1], af[mi][2], af[mi][3],
                                bm[p][1], bm[p][3]);
                }
        }
    }
#undef ISSUE_STAGE

#pragma unroll
    for (int mi = 0; mi < 2; mi++) {
#pragma unroll
        for (int nj = 0; nj < 8; nj++) {
            int row = m0 + wm + mi*16 + (lane >> 2);
            int col = n0 + wn + nj*8 + (lane & 3)*2;
            float b0 = bias[col], b1 = bias[col+1];
            float2 v0 = { c[mi][nj][0] + b0, c[mi][nj][1] + b1 };
            float2 v1 = { c[mi][nj][2] + b0, c[mi][nj][3] + b1 };
            if (MODE == 0) {
                *(float2*)&out[(size_t)row*C_ + col]     = v0;
                *(float2*)&out[(size_t)(row+8)*C_ + col] = v1;
            } else {
                int which = col >> 10;
                int h = (col & 1023) >> 6;
                int d = col & 63;
                int b = row >> 11, t = row & 2047;
                if (which == 2) {
                    size_t vb0 = ((size_t)(b*H_ + h)*T_ + t    )*64 + d;
                    size_t vb1 = ((size_t)(b*H_ + h)*T_ + t + 8)*64 + d;
                    __half2 h0, h1;
                    h0.x = __float2half_rn(v0.x);
                    h0.y = __float2half_rn(v0.y);
                    h1.x = __float2half_rn(v1.x);
                    h1.y = __float2half_rn(v1.y);
                    *(__half2*)&g_vs[vb0] = h0;
                    *(__half2*)&g_vs[vb1] = h1;
                } else {
                    float* dst = (which == 0) ? g_q : g_k;
                    size_t base0 = ((size_t)(b*H_ + h)*T_ + t    )*D_ + d;
                    size_t base1 = ((size_t)(b*H_ + h)*T_ + t + 8)*D_ + d;
                    *(float2*)&dst[base0] = v0;
                    *(float2*)&dst[base1] = v1;
                }
            }
        }
    }
}

// ---------------------------------------------------------------------------
// RoPE on q,k (fp32 in) -> q fp16 [hi64|lo64] (g_qs), k fp16 hi only (g_ks).
// ---------------------------------------------------------------------------
__global__ void rope_kernel()
{
    int idx = blockIdx.x * blockDim.x + threadIdx.x;
    int d  = idx & 31;
    int t  = (idx >> 5) & (T_ - 1);
    int bh = idx >> 16;
    size_t base = ((size_t)bh * T_ + t) * D_;
    size_t oqb  = ((size_t)bh * T_ + t) * 128;
    size_t okb  = ((size_t)bh * T_ + t) * 64;

    const float L2_10000_OVER_32 = 13.287712379549449f / 32.0f;
    float f = exp2f(-(float)d * L2_10000_OVER_32);
    float ang = (float)t * f;
    float s, cc;
    sincosf(ang, &s, &cc);

    float q1 = g_q[base + d], q2 = g_q[base + d + 32];
    float o1 = q1*cc - q2*s;
    float o2 = q2*cc + q1*s;
    __half h1 = __float2half_rn(o1);
    __half h2 = __float2half_rn(o2);
    g_qs[oqb + d]           = h1;
    g_qs[oqb + d + 32]      = h2;
    g_qs[oqb + 64 + d]      = __float2half_rn(o1 - __half2float(h1));
    g_qs[oqb + 64 + d + 32] = __float2half_rn(o2 - __half2float(h2));

    float k1 = g_k[base + d], k2 = g_k[base + d + 32];
    o1 = k1*cc - k2*s;
    o2 = k2*cc + k1*s;
    g_ks[okb + d]      = __float2half_rn(o1);
    g_ks[okb + d + 32] = __float2half_rn(o2);
}

// ---------------------------------------------------------------------------
// fp16 tensor-core causal flash attention (proven R15):
//   S = (q_hi + q_lo) . k_hi     (8 k16-steps)
//   O = (p_hi + p_lo) . v_hi     (8 k16-steps)
// K/V hi-only tiles, cp.async double-buffered.
// ---------------------------------------------------------------------------
#define QST 136
#define KST 72
#define VST 72
#define SC_ 0.125f
#define ATTN_SMEM ((128*QST + 2*64*KST + 2*64*VST) * 2)

__global__ void __launch_bounds__(256) attn_mma()
{
    extern __shared__ __align__(16) __half smA[];
    __half* Qs = smA;                 // [128][QST]: [q_hi(64) | q_lo(64)]
    __half* Ks = Qs + 128*QST;        // 2 x [64][KST] hi only
    __half* Vs = Ks + 2*64*KST;       // 2 x [64][VST] hi only

    const int qt  = (int)gridDim.x - 1 - (int)blockIdx.x;
    const int bh  = blockIdx.y;
    const int tid = threadIdx.x;
    const int wid = tid >> 5;
    const int lane = tid & 31;
    const int lg = lane >> 2;
    const int lq = lane & 3;
    const int lrow = lane & 15;
    const int lcol = (lane >> 4) << 3;

    const int jmax = 2*qt + 1;

#define ATTN_LOAD(jtv, bufv)                                                  \
    do {                                                                      \
        const __half* ksrc = g_ks + ((size_t)bh*T_ + (jtv)*64)*64;            \
        const __half* vsrc = g_vs + ((size_t)bh*T_ + (jtv)*64)*64;            \
        __half* Kb = Ks + (bufv)*64*KST;                                      \
        __half* Vb = Vs + (bufv)*64*VST;                                      \
        _Pragma("unroll")                                                     \
        for (int i = 0; i < 2; i++) {                                         \
            int idx = tid + i*256;                                            \
            int r = idx >> 3, u = idx & 7;                                    \
            unsigned int ka = (unsigned int)__cvta_generic_to_shared(         \
                &Kb[r*KST + u*8]);                                            \
            CP_ASYNC16(ka, &ksrc[r*64 + u*8]);                                \
            unsigned int va = (unsigned int)__cvta_generic_to_shared(         \
                &Vb[r*VST + u*8]);                                            \
            CP_ASYNC16(va, &vsrc[r*64 + u*8]);                                \
        }                                                                     \
        asm volatile("cp.async.commit_group;\n");                             \
    } while (0)

    ATTN_LOAD(0, 0);

    const __half* qsrc = g_qs + ((size_t)bh*T_ + qt*128)*128;
#pragma unroll
    for (int i = 0; i < 8; i++) {
        int idx = tid + i*256;
        int r = idx >> 4, u = (idx & 15) * 8;
        *(uint4*)&Qs[r*QST + u] = *(const uint4*)&qsrc[r*128 + u];
    }

    float m2[2] = {-CUDART_INF_F, -CUDART_INF_F};
    float l2[2] = {0.f, 0.f};
    float oc[8][4];
#pragma unroll
    for (int j = 0; j < 8; j++)
#pragma unroll
        for (int r = 0; r < 4; r++) oc[j][r] = 0.f;

    for (int jt = 0; jt <= jmax; jt++) {
        const int buf = jt & 1;
        if (jt + 1 <= jmax) {
            ATTN_LOAD(jt + 1, buf ^ 1);
            asm volatile("cp.async.wait_group %0;\n" :: "n"(1));
        } else {
            asm volatile("cp.async.wait_group %0;\n" :: "n"(0));
        }
        __syncthreads();

        const __half* Kb = Ks + buf*64*KST;
        const __half* Vb = Vs + buf*64*VST;

        float sc[8][4];
#pragma unroll
        for (int j = 0; j < 8; j++)
#pragma unroll
            for (int r = 0; r < 4; r++) sc[j][r] = 0.f;

#pragma unroll
        for (int ks = 0; ks < 8; ks++) {
            int kk16 = (ks & 3) * 16;
            int Aoff = (ks >= 4) ? 64 : 0;
            unsigned int af[4];
            LDSM_X4(af[0], af[1], af[2], af[3],
                    &Qs[(wid*16 + lrow)*QST + Aoff + kk16 + lcol]);
#pragma unroll
            for (int p = 0; p < 4; p++) {
                unsigned int bm0, bm1, bm2, bm3;
                LDSM_X4(bm0, bm1, bm2, bm3,
                        &Kb[(p*16 + lrow)*KST + kk16 + lcol]);
                MMA16816F16(sc[2*p],   af[0], af[1], af[2], af[3], bm0, bm2);
                MMA16816F16(sc[2*p+1], af[0], af[1], af[2], af[3], bm1, bm3);
            }
        }

        const bool needmask = (jt >= 2*qt);
        float rowm[2] = {-CUDART_INF_F, -CUDART_INF_F};
#pragma unroll
        for (int nj = 0; nj < 8; nj++) {
            if (needmask) {
                int kg  = jt*64 + nj*8 + lq*2;
                int qr0 = qt*128 + wid*16 + lg;
#pragma unroll
                for (int e = 0; e < 4; e++) {
                    if (kg + (e & 1) > qr0 + (e >> 1)*8) sc[nj][e] = -CUDART_INF_F;
                }
            }
            rowm[0] = fmaxf(rowm[0], fmaxf(sc[nj][0], sc[nj][1]));
            rowm[1] = fmaxf(rowm[1], fmaxf(sc[nj][2], sc[nj][3]));
        }
#pragma unroll
        for (int off = 1; off <= 2; off <<= 1) {
            rowm[0] = fmaxf(rowm[0], __shfl_xor_sync(0xffffffffu, rowm[0], off));
            rowm[1] = fmaxf(rowm[1], __shfl_xor_sync(0xffffffffu, rowm[1], off));
        }
        float corr[2];
#pragma unroll
        for (int h = 0; h < 2; h++) {
            float mn = fmaxf(m2[h], rowm[h]);
            corr[h] = __expf((m2[h] - mn) * SC_);
            m2[h] = mn;
        }
        float rs[2] = {0.f, 0.f};
        unsigned int ph[8][2], pl[8][2];
#pragma unroll
        for (int nj = 0; nj < 8; nj++) {
            float p0 = __expf((sc[nj][0] - m2[0]) * SC_);
            float p1 = __expf((sc[nj][1] - m2[0]) * SC_);
            float p2 = __expf((sc[nj][2] - m2[1]) * SC_);
            float p3 = __expf((sc[nj][3] - m2[1]) * SC_);
            rs[0] += p0 + p1;
            rs[1] += p2 + p3;
            __half2 h01, h23, l01, l23;
            h01.x = __float2half_rn(p0); h01.y = __float2half_rn(p1);
            l01.x = __float2half_rn(p0 - __half2float(h01.x));
            l01.y = __float2half_rn(p1 - __half2float(h01.y));
            h23.x = __float2half_rn(p2); h23.y = __float2half_rn(p3);
            l23.x = __float2half_rn(p2 - __half2float(h23.x));
            l23.y = __float2half_rn(p3 - __half2float(h23.y));
            ph[nj][0] = *(unsigned int*)&h01;
            ph[nj][1] = *(unsigned int*)&h23;
            pl[nj][0] = *(unsigned int*)&l01;
            pl[nj][1] = *(unsigned int*)&l23;
        }
#pragma unroll
        for (int off = 1; off <= 2; off <<= 1) {
            rs[0] += __shfl_xor_sync(0xffffffffu, rs[0], off);
            rs[1] += __shfl_xor_sync(0xffffffffu, rs[1], off);
        }
#pragma unroll
        for (int h = 0; h < 2; h++) l2[h] = l2[h]*corr[h] + rs[h];
#pragma unroll
        for (int nj = 0; nj < 8; nj++) {
            oc[nj][0] *= corr[0]; oc[nj][1] *= corr[0];
            oc[nj][2] *= corr[1]; oc[nj][3] *= corr[1];
        }

#pragma unroll
        for (int ks = 0; ks < 8; ks++) {
            int kk = ks & 3;
            unsigned int a0, a1, a2, a3;
            if (ks < 4) {
                a0 = ph[2*kk][0]; a1 = ph[2*kk][1];
                a2 = ph[2*kk+1][0]; a3 = ph[2*kk+1][1];
            } else {
                a0 = pl[2*kk][0]; a1 = pl[2*kk][1];
                a2 = pl[2*kk+1][0]; a3 = pl[2*kk+1][1];
            }
            int kcV = kk*16;
            int g = lane >> 3, rr = lane & 7;
#pragma unroll
            for (int njp = 0; njp < 4; njp++) {
                unsigned int addr = (unsigned int)__cvta_generic_to_shared(
                    &Vb[(kcV + rr + (g & 1)*8)*VST + njp*16 + (g >> 1)*8]);
                unsigned int b0, b1, b2, b3;
                asm volatile(
                    "ldmatrix.sync.aligned.m8n8.x4.trans.shared.b16 {%0,%1,%2,%3}, [%4];\n"
                    : "=r"(b0), "=r"(b1), "=r"(b2), "=r"(b3) : "r"(addr));
                MMA16816F16(oc[njp*2],   a0, a1, a2, a3, b0, b1);
                MMA16816F16(oc[njp*2+1], a0, a1, a2, a3, b2, b3);
            }
        }
        __syncthreads();
    }
#undef ATTN_LOAD

    // epilogue: normalize, write fp16 [hi|lo] into g_ys (K''=2048)
    int b = bh >> 4, h = bh & 15;
#pragma unroll
    for (int half = 0; half < 2; half++) {
        float inv = 1.0f / l2[half];
        int trow = qt*128 + wid*16 + lg + half*8;
        size_t rowbase = ((size_t)b*T_ + trow) * (size_t)KP2;
        int c0 = h*64 + lq*2;
#pragma unroll
        for (int nj = 0; nj < 8; nj++) {
            float y0 = oc[nj][half*2]   * inv;
            float y1 = oc[nj][half*2+1] * inv;
            __half2 hp, lp;
            hp.x = __float2half_rn(y0);
            hp.y = __float2half_rn(y1);
            lp.x = __float2half_rn(y0 - __half2float(hp.x));
            lp.y = __float2half_rn(y1 - __half2float(hp.y));
            int c = c0 + nj*8;
            *(__half2*)&g_ys[rowbase + c]        = hp;
            *(__half2*)&g_ys[rowbase + 1024 + c] = lp;
        }
    }
}

// ---------------------------------------------------------------------------
extern "C" void kernel_launch(void* const* d_in, const int* in_sizes, int n_in,
                              void* d_out, int out_size)
{
    const float* x      = (const float*)d_in[0];
    const float* W_attn = (const float*)d_in[1];
    const float* b_attn = (const float*)d_in[2];
    const float* W_proj = (const float*)d_in[3];
    const float* b_proj = (const float*)d_in[4];
    float* out = (float*)d_out;

    split_x_kernel<<<(M_*C_/4 + 255)/256, 256>>>(x);
    split_w_kernel<<<(3*C_*C_/4 + 255)/256, 256>>>(W_attn);
    split_wp_kernel<<<(C_*C_/4 + 255)/256, 256>>>(W_proj);

    cudaFuncSetAttribute(mma_gemm<1>, cudaFuncAttributeMaxDynamicSharedMemorySize, GEMM_SMEM);
    cudaFuncSetAttribute(mma_gemm<0>, cudaFuncAttributeMaxDynamicSharedMemorySize, GEMM_SMEM);

    mma_gemm<1><<<dim3(3*C_/128, M_/256), 512, GEMM_SMEM>>>(b_attn, nullptr);

    rope_kernel<<<(B_*H_*T_*32)/256, 256>>>();

    cudaFuncSetAttribute(attn_mma, cudaFuncAttributeMaxDynamicSharedMemorySize, ATTN_SMEM);
    attn_mma<<<dim3(T_/128, B_*H_), 256, ATTN_SMEM>>>();

    mma_gemm<0><<<dim3(C_/128, M_/256), 512, GEMM_SMEM>>>(b_proj, out);
}

// round 17
// speedup vs baseline: 2.6723x; 1.3292x over previous
#include <cuda_runtime.h>
#include <cuda_bf16.h>
#include <cuda_fp16.h>
#include <math_constants.h>
#include <cstdint>

// Problem constants
#define B_  2
#define T_  2048
#define C_  1024
#define H_  16
#define D_  64
#define M_  (B_*T_)          // 4096 rows
#define BHTD (B_*H_*T_*D_)

// Scratch (device globals, referenced directly from kernels)
__device__ float g_q[BHTD];
__device__ float g_k[BHTD];
__device__ __half g_qs[(size_t)BHTD];                // q fp16 hi [bh][t][64]
__device__ __half g_ks[(size_t)BHTD];                // k fp16 hi
__device__ __half g_vs[(size_t)BHTD];                // v fp16 hi
__device__ __half g_xs[(size_t)M_ * C_];             // x fp16 hi [4096,1024]
__device__ __half g_ws[(size_t)3*C_ * C_];           // W_attn fp16 hi
__device__ __half g_ys[(size_t)M_ * C_];             // y fp16 hi [4096,1024]
__device__ __half g_wps[(size_t)C_ * C_];            // W_proj fp16 hi

// ---------------------------------------------------------------------------
// fp32 -> fp16 conversions.
// ---------------------------------------------------------------------------
__global__ void split_x_kernel(const float* __restrict__ src)
{
    int idx = blockIdx.x * blockDim.x + threadIdx.x;
    if (idx >= M_*C_/4) return;
    float4 v = ((const float4*)src)[idx];
    __half2 a, b;
    a.x = __float2half_rn(v.x); a.y = __float2half_rn(v.y);
    b.x = __float2half_rn(v.z); b.y = __float2half_rn(v.w);
    *(__half2*)&g_xs[(size_t)idx*4]     = a;
    *(__half2*)&g_xs[(size_t)idx*4 + 2] = b;
}

__global__ void split_w_kernel(const float* __restrict__ src)
{
    int idx = blockIdx.x * blockDim.x + threadIdx.x;
    if (idx >= 3*C_*C_/4) return;
    float4 v = ((const float4*)src)[idx];
    __half2 a, b;
    a.x = __float2half_rn(v.x); a.y = __float2half_rn(v.y);
    b.x = __float2half_rn(v.z); b.y = __float2half_rn(v.w);
    *(__half2*)&g_ws[(size_t)idx*4]     = a;
    *(__half2*)&g_ws[(size_t)idx*4 + 2] = b;
}

__global__ void split_wp_kernel(const float* __restrict__ src)
{
    int idx = blockIdx.x * blockDim.x + threadIdx.x;
    if (idx >= C_*C_/4) return;
    float4 v = ((const float4*)src)[idx];
    __half2 a, b;
    a.x = __float2half_rn(v.x); a.y = __float2half_rn(v.y);
    b.x = __float2half_rn(v.z); b.y = __float2half_rn(v.w);
    *(__half2*)&g_wps[(size_t)idx*4]     = a;
    *(__half2*)&g_wps[(size_t)idx*4 + 2] = b;
}

// ---------------------------------------------------------------------------
// Shared PTX helpers
// ---------------------------------------------------------------------------
#define MMA16816F16(C4, A0,A1,A2,A3, B0,B1)                                   \
    asm volatile(                                                             \
        "mma.sync.aligned.m16n8k16.row.col.f32.f16.f16.f32 "                  \
        "{%0,%1,%2,%3}, {%4,%5,%6,%7}, {%8,%9}, {%0,%1,%2,%3};\n"             \
        : "+f"((C4)[0]), "+f"((C4)[1]), "+f"((C4)[2]), "+f"((C4)[3])          \
        : "r"(A0), "r"(A1), "r"(A2), "r"(A3), "r"(B0), "r"(B1))

#define LDSM_X4(R0,R1,R2,R3, ptr)                                             \
    do {                                                                      \
        unsigned int _a = (unsigned int)__cvta_generic_to_shared(ptr);        \
        asm volatile(                                                         \
            "ldmatrix.sync.aligned.m8n8.x4.shared.b16 {%0,%1,%2,%3}, [%4];\n" \
            : "=r"(R0), "=r"(R1), "=r"(R2), "=r"(R3) : "r"(_a));              \
    } while (0)

#define CP_ASYNC16(smem_u32, gptr)                                            \
    asm volatile("cp.async.cg.shared.global [%0], [%1], 16;\n"                \
                 :: "r"(smem_u32), "l"(gptr))

// ---------------------------------------------------------------------------
// fp16 tensor-core GEMM, K=1024 plain fp16 (proven template).
// MODE 1: x*W_attn^T + b_attn -> q,k fp32 [B,H,T,D]; v fp16 hi into g_vs
// MODE 0: y*W_proj^T + b_proj -> out row-major [M,1024]
// ---------------------------------------------------------------------------
#define SSTRIDE 40
#define GSTAGES 4
#define GEMM_SMEM ((GSTAGES*(256+128)*SSTRIDE)*2)

template<int MODE>
__global__ void __launch_bounds__(512) mma_gemm(
    const float* __restrict__ bias, float* __restrict__ out)
{
    const __half* A  = (MODE == 1) ? g_xs : g_ys;
    const __half* Bw = (MODE == 1) ? g_ws : g_wps;

    extern __shared__ __align__(16) __half gsm[];
    __half* As = gsm;                          // [GSTAGES][256*SSTRIDE]
    __half* Bs = gsm + GSTAGES*256*SSTRIDE;    // [GSTAGES][128*SSTRIDE]

    const int tid  = threadIdx.x;
    const int wid  = tid >> 5;
    const int lane = tid & 31;
    const int m0 = blockIdx.y * 256;
    const int n0 = blockIdx.x * 128;
    const int wm = (wid >> 1) * 32;
    const int wn = (wid & 1) * 64;
    const int lrow = lane & 15;
    const int lcol = (lane >> 4) << 3;

    const __half* Ag = A  + (size_t)m0 * C_;
    const __half* Bg = Bw + (size_t)n0 * C_;

    const int brow = tid >> 2, bseg = tid & 3;

    float c[2][8][4];
#pragma unroll
    for (int i = 0; i < 2; i++)
#pragma unroll
        for (int j = 0; j < 8; j++)
#pragma unroll
            for (int r = 0; r < 4; r++) c[i][j][r] = 0.f;

    const int nt = C_ / 32;   // 32

#define ISSUE_STAGE(stage, k0)                                                \
    do {                                                                      \
        __half* asb = As + (stage)*256*SSTRIDE;                               \
        __half* bsb = Bs + (stage)*128*SSTRIDE;                               \
        _Pragma("unroll")                                                     \
        for (int i = 0; i < 2; i++) {                                         \
            int idx = tid + 512*i, row = idx >> 2, seg = idx & 3;             \
            unsigned int sa = (unsigned int)__cvta_generic_to_shared(         \
                &asb[row*SSTRIDE + seg*8]);                                   \
            CP_ASYNC16(sa, Ag + (size_t)row*C_ + (k0) + seg*8);               \
        }                                                                     \
        {                                                                     \
            unsigned int sb = (unsigned int)__cvta_generic_to_shared(         \
                &bsb[brow*SSTRIDE + bseg*8]);                                 \
            CP_ASYNC16(sb, Bg + (size_t)brow*C_ + (k0) + bseg*8);             \
        }                                                                     \
        asm volatile("cp.async.commit_group;\n");                             \
    } while (0)

    ISSUE_STAGE(0, 0);
    ISSUE_STAGE(1, 32);
    ISSUE_STAGE(2, 64);

    for (int kt = 0; kt < nt; kt++) {
        const int stage = kt % GSTAGES;
        asm volatile("cp.async.wait_group %0;\n" :: "n"(2));
        __syncthreads();

        if (kt + 3 < nt) {
            ISSUE_STAGE((kt + 3) % GSTAGES, (kt + 3) * 32);
        }

        const __half* asb = As + stage*256*SSTRIDE;
        const __half* bsb = Bs + stage*128*SSTRIDE;

#pragma unroll
        for (int ks = 0; ks < 2; ks++) {
            const int k16 = ks * 16;
            unsigned int af[2][4];
#pragma unroll
            for (int mi = 0; mi < 2; mi++) {
                LDSM_X4(af[mi][0], af[mi][1], af[mi][2], af[mi][3],
                        &asb[(wm + mi*16 + lrow)*SSTRIDE + k16 + lcol]);
            }
            unsigned int bm[4][4];
#pragma unroll
            for (int p = 0; p < 4; p++) {
                LDSM_X4(bm[p][0], bm[p][1], bm[p][2], bm[p][3],
                        &bsb[(wn + p*16 + lrow)*SSTRIDE + k16 + lcol]);
            }
#pragma unroll
            for (int mi = 0; mi < 2; mi++)
#pragma unroll
                for (int p = 0; p < 4; p++) {
                    MMA16816F16(c[mi][2*p],   af[mi][0], af[mi][1], af[mi][2], af[mi][3],
                                bm[p][0], bm[p][2]);
                    MMA16816F16(c[mi][2*p+1], af[mi][0], af[mi][1], af[mi][2], af[mi][3],
                                bm[p][1], bm[p][3]);
                }
        }
    }
#undef ISSUE_STAGE

#pragma unroll
    for (int mi = 0; mi < 2; mi++) {
#pragma unroll
        for (int nj = 0; nj < 8; nj++) {
            int row = m0 + wm + mi*16 + (lane >> 2);
            int col = n0 + wn + nj*8 + (lane & 3)*2;
            float b0 = bias[col], b1 = bias[col+1];
            float2 v0 = { c[mi][nj][0] + b0, c[mi][nj][1] + b1 };
            float2 v1 = { c[mi][nj][2] + b0, c[mi][nj][3] + b1 };
            if (MODE == 0) {
                *(float2*)&out[(size_t)row*C_ + col]     = v0;
                *(float2*)&out[(size_t)(row+8)*C_ + col] = v1;
            } else {
                int which = col >> 10;
                int h = (col & 1023) >> 6;
                int d = col & 63;
                int b = row >> 11, t = row & 2047;
                if (which == 2) {
                    size_t vb0 = ((size_t)(b*H_ + h)*T_ + t    )*64 + d;
                    size_t vb1 = ((size_t)(b*H_ + h)*T_ + t + 8)*64 + d;
                    __half2 h0, h1;
                    h0.x = __float2half_rn(v0.x);
                    h0.y = __float2half_rn(v0.y);
                    h1.x = __float2half_rn(v1.x);
                    h1.y = __float2half_rn(v1.y);
                    *(__half2*)&g_vs[vb0] = h0;
                    *(__half2*)&g_vs[vb1] = h1;
                } else {
                    float* dst = (which == 0) ? g_q : g_k;
                    size_t base0 = ((size_t)(b*H_ + h)*T_ + t    )*D_ + d;
                    size_t base1 = ((size_t)(b*H_ + h)*T_ + t + 8)*D_ + d;
                    *(float2*)&dst[base0] = v0;
                    *(float2*)&dst[base1] = v1;
                }
            }
        }
    }
}

// ---------------------------------------------------------------------------
// RoPE on q,k (fp32 in) -> fp16 hi only (g_qs, g_ks).
// ---------------------------------------------------------------------------
__global__ void rope_kernel()
{
    int idx = blockIdx.x * blockDim.x + threadIdx.x;
    int d  = idx & 31;
    int t  = (idx >> 5) & (T_ - 1);
    int bh = idx >> 16;
    size_t base = ((size_t)bh * T_ + t) * D_;
    size_t ob   = ((size_t)bh * T_ + t) * 64;

    const float L2_10000_OVER_32 = 13.287712379549449f / 32.0f;
    float f = exp2f(-(float)d * L2_10000_OVER_32);
    float ang = (float)t * f;
    float s, cc;
    sincosf(ang, &s, &cc);

    float q1 = g_q[base + d], q2 = g_q[base + d + 32];
    g_qs[ob + d]      = __float2half_rn(q1*cc - q2*s);
    g_qs[ob + d + 32] = __float2half_rn(q2*cc + q1*s);

    float k1 = g_k[base + d], k2 = g_k[base + d + 32];
    g_ks[ob + d]      = __float2half_rn(k1*cc - k2*s);
    g_ks[ob + d + 32] = __float2half_rn(k2*cc + k1*s);
}

// ---------------------------------------------------------------------------
// fp16 tensor-core causal flash attention, all operands hi-only:
//   S = q_hi . k_hi   (4 k16-steps)
//   O = p_hi . v_hi   (4 k16-steps)
// cp.async double-buffered K/V (proven R13 pattern).
// ---------------------------------------------------------------------------
#define QST 72
#define KST 72
#define VST 72
#define SC_ 0.125f
#define ATTN_SMEM ((128*QST + 2*64*KST + 2*64*VST) * 2)

__global__ void __launch_bounds__(256) attn_mma()
{
    extern __shared__ __align__(16) __half smA[];
    __half* Qs = smA;                 // [128][QST] hi only
    __half* Ks = Qs + 128*QST;        // 2 x [64][KST]
    __half* Vs = Ks + 2*64*KST;       // 2 x [64][VST]

    const int qt  = (int)gridDim.x - 1 - (int)blockIdx.x;
    const int bh  = blockIdx.y;
    const int tid = threadIdx.x;
    const int wid = tid >> 5;
    const int lane = tid & 31;
    const int lg = lane >> 2;
    const int lq = lane & 3;
    const int lrow = lane & 15;
    const int lcol = (lane >> 4) << 3;

    const int jmax = 2*qt + 1;

#define ATTN_LOAD(jtv, bufv)                                                  \
    do {                                                                      \
        const __half* ksrc = g_ks + ((size_t)bh*T_ + (jtv)*64)*64;            \
        const __half* vsrc = g_vs + ((size_t)bh*T_ + (jtv)*64)*64;            \
        __half* Kb = Ks + (bufv)*64*KST;                                      \
        __half* Vb = Vs + (bufv)*64*VST;                                      \
        _Pragma("unroll")                                                     \
        for (int i = 0; i < 2; i++) {                                         \
            int idx = tid + i*256;                                            \
            int r = idx >> 3, u = idx & 7;                                    \
            unsigned int ka = (unsigned int)__cvta_generic_to_shared(         \
                &Kb[r*KST + u*8]);                                            \
            CP_ASYNC16(ka, &ksrc[r*64 + u*8]);                                \
            unsigned int va = (unsigned int)__cvta_generic_to_shared(         \
                &Vb[r*VST + u*8]);                                            \
            CP_ASYNC16(va, &vsrc[r*64 + u*8]);                                \
        }                                                                     \
        asm volatile("cp.async.commit_group;\n");                             \
    } while (0)

    ATTN_LOAD(0, 0);

    const __half* qsrc = g_qs + ((size_t)bh*T_ + qt*128)*64;
#pragma unroll
    for (int i = 0; i < 4; i++) {
        int idx = tid + i*256;
        int r = idx >> 3, u = (idx & 7) * 8;
        *(uint4*)&Qs[r*QST + u] = *(const uint4*)&qsrc[r*64 + u];
    }

    float m2[2] = {-CUDART_INF_F, -CUDART_INF_F};
    float l2[2] = {0.f, 0.f};
    float oc[8][4];
#pragma unroll
    for (int j = 0; j < 8; j++)
#pragma unroll
        for (int r = 0; r < 4; r++) oc[j][r] = 0.f;

    for (int jt = 0; jt <= jmax; jt++) {
        const int buf = jt & 1;
        if (jt + 1 <= jmax) {
            ATTN_LOAD(jt + 1, buf ^ 1);
            asm volatile("cp.async.wait_group %0;\n" :: "n"(1));
        } else {
            asm volatile("cp.async.wait_group %0;\n" :: "n"(0));
        }
        __syncthreads();

        const __half* Kb = Ks + buf*64*KST;
        const __half* Vb = Vs + buf*64*VST;

        // ---- S = q_hi . k_hi ----
        float sc[8][4];
#pragma unroll
        for (int j = 0; j < 8; j++)
#pragma unroll
            for (int r = 0; r < 4; r++) sc[j][r] = 0.f;

#pragma unroll
        for (int ks = 0; ks < 4; ks++) {
            int kk16 = ks * 16;
            unsigned int af[4];
            LDSM_X4(af[0], af[1], af[2], af[3],
                    &Qs[(wid*16 + lrow)*QST + kk16 + lcol]);
#pragma unroll
            for (int p = 0; p < 4; p++) {
                unsigned int bm0, bm1, bm2, bm3;
                LDSM_X4(bm0, bm1, bm2, bm3,
                        &Kb[(p*16 + lrow)*KST + kk16 + lcol]);
                MMA16816F16(sc[2*p],   af[0], af[1], af[2], af[3], bm0, bm2);
                MMA16816F16(sc[2*p+1], af[0], af[1], af[2], af[3], bm1, bm3);
            }
        }

        // ---- mask + online softmax ----
        const bool needmask = (jt >= 2*qt);
        float rowm[2] = {-CUDART_INF_F, -CUDART_INF_F};
#pragma unroll
        for (int nj = 0; nj < 8; nj++) {
            if (needmask) {
                int kg  = jt*64 + nj*8 + lq*2;
                int qr0 = qt*128 + wid*16 + lg;
#pragma unroll
                for (int e = 0; e < 4; e++) {
                    if (kg + (e & 1) > qr0 + (e >> 1)*8) sc[nj][e] = -CUDART_INF_F;
                }
            }
            rowm[0] = fmaxf(rowm[0], fmaxf(sc[nj][0], sc[nj][1]));
            rowm[1] = fmaxf(rowm[1], fmaxf(sc[nj][2], sc[nj][3]));
        }
#pragma unroll
        for (int off = 1; off <= 2; off <<= 1) {
            rowm[0] = fmaxf(rowm[0], __shfl_xor_sync(0xffffffffu, rowm[0], off));
            rowm[1] = fmaxf(rowm[1], __shfl_xor_sync(0xffffffffu, rowm[1], off));
        }
        float corr[2];
#pragma unroll
        for (int h = 0; h < 2; h++) {
            float mn = fmaxf(m2[h], rowm[h]);
            corr[h] = __expf((m2[h] - mn) * SC_);
            m2[h] = mn;
        }
        float rs[2] = {0.f, 0.f};
        unsigned int ph[8][2];
#pragma unroll
        for (int nj = 0; nj < 8; nj++) {
            float p0 = __expf((sc[nj][0] - m2[0]) * SC_);
            float p1 = __expf((sc[nj][1] - m2[0]) * SC_);
            float p2 = __expf((sc[nj][2] - m2[1]) * SC_);
            float p3 = __expf((sc[nj][3] - m2[1]) * SC_);
            rs[0] += p0 + p1;
            rs[1] += p2 + p3;
            __half2 h01, h23;
            h01.x = __float2half_rn(p0); h01.y = __float2half_rn(p1);
            h23.x = __float2half_rn(p2); h23.y = __float2half_rn(p3);
            ph[nj][0] = *(unsigned int*)&h01;
            ph[nj][1] = *(unsigned int*)&h23;
        }
#pragma unroll
        for (int off = 1; off <= 2; off <<= 1) {
            rs[0] += __shfl_xor_sync(0xffffffffu, rs[0], off);
            rs[1] += __shfl_xor_sync(0xffffffffu, rs[1], off);
        }
#pragma unroll
        for (int h = 0; h < 2; h++) l2[h] = l2[h]*corr[h] + rs[h];
#pragma unroll
        for (int nj = 0; nj < 8; nj++) {
            oc[nj][0] *= corr[0]; oc[nj][1] *= corr[0];
            oc[nj][2] *= corr[1]; oc[nj][3] *= corr[1];
        }

        // ---- O += p_hi . v_hi ----
#pragma unroll
        for (int ks = 0; ks < 4; ks++) {
            unsigned int a0 = ph[2*ks][0], a1 = ph[2*ks][1];
            unsigned int a2 = ph[2*ks+1][0], a3 = ph[2*ks+1][1];
            int kcV = ks*16;
            int g = lane >> 3, rr = lane & 7;
#pragma unroll
            for (int njp = 0; njp < 4; njp++) {
                unsigned int addr = (unsigned int)__cvta_generic_to_shared(
                    &Vb[(kcV + rr + (g & 1)*8)*VST + njp*16 + (g >> 1)*8]);
                unsigned int b0, b1, b2, b3;
                asm volatile(
                    "ldmatrix.sync.aligned.m8n8.x4.trans.shared.b16 {%0,%1,%2,%3}, [%4];\n"
                    : "=r"(b0), "=r"(b1), "=r"(b2), "=r"(b3) : "r"(addr));
                MMA16816F16(oc[njp*2],   a0, a1, a2, a3, b0, b1);
                MMA16816F16(oc[njp*2+1], a0, a1, a2, a3, b2, b3);
            }
        }
        __syncthreads();
    }
#undef ATTN_LOAD

    // epilogue: normalize, write fp16 hi into g_ys [M,1024]
    int b = bh >> 4, h = bh & 15;
#pragma unroll
    for (int half = 0; half < 2; half++) {
        float inv = 1.0f / l2[half];
        int trow = qt*128 + wid*16 + lg + half*8;
        size_t rowbase = ((size_t)b*T_ + trow) * (size_t)C_;
        int c0 = h*64 + lq*2;
#pragma unroll
        for (int nj = 0; nj < 8; nj++) {
            float y0 = oc[nj][half*2]   * inv;
            float y1 = oc[nj][half*2+1] * inv;
            __half2 hp;
            hp.x = __float2half_rn(y0);
            hp.y = __float2half_rn(y1);
            *(__half2*)&g_ys[rowbase + c0 + nj*8] = hp;
        }
    }
}

// ---------------------------------------------------------------------------
extern "C" void kernel_launch(void* const* d_in, const int* in_sizes, int n_in,
                              void* d_out, int out_size)
{
    const float* x      = (const float*)d_in[0];
    const float* W_attn = (const float*)d_in[1];
    const float* b_attn = (const float*)d_in[2];
    const float* W_proj = (const float*)d_in[3];
    const float* b_proj = (const float*)d_in[4];
    float* out = (float*)d_out;

    split_x_kernel<<<(M_*C_/4 + 255)/256, 256>>>(x);
    split_w_kernel<<<(3*C_*C_/4 + 255)/256, 256>>>(W_attn);
    split_wp_kernel<<<(C_*C_/4 + 255)/256, 256>>>(W_proj);

    cudaFuncSetAttribute(mma_gemm<1>, cudaFuncAttributeMaxDynamicSharedMemorySize, GEMM_SMEM);
    cudaFuncSetAttribute(mma_gemm<0>, cudaFuncAttributeMaxDynamicSharedMemorySize, GEMM_SMEM);

    mma_gemm<1><<<dim3(3*C_/128, M_/256), 512, GEMM_SMEM>>>(b_attn, nullptr);

    rope_kernel<<<(B_*H_*T_*32)/256, 256>>>();

    cudaFuncSetAttribute(attn_mma, cudaFuncAttributeMaxDynamicSharedMemorySize, ATTN_SMEM);
    attn_mma<<<dim3(T_/128, B_*H_), 256, ATTN_SMEM>>>();

    mma_gemm<0><<<dim3(C_/128, M_/256), 512, GEMM_SMEM>>>(b_proj, out);
}